// round 1
// baseline (speedup 1.0000x reference)
#include <cuda_runtime.h>
#include <cuda_bf16.h>
#include <cstddef>

// ---------------------------------------------------------------------------
// OCR head: softmax-gather context + object attention + concat projection.
// Shapes: B=4, C=512, N=128*128=16384, KEY=256, Kctx=512.
// Strategy (round 1 baseline): FP32 tiled SGEMM (128x128x8, 8x8 microtile),
// fused bias+ReLU epilogue, split-K for the K=16384 context GEMM,
// smem-resident row softmaxes. All scratch in __device__ globals (no allocs).
// ---------------------------------------------------------------------------

#define BATCH 4
#define CDIM 512
#define NDIM 16384
#define KEYD 256

// Scratch pools (reused across stages):
__device__ float g_bufA[33554432]; // pw [B,512,N], later sim [B,N,512]
__device__ float g_bufB[16777216]; // t1 [B,256,N], later attn ctx [B,256,N]
__device__ float g_bufC[16777216]; // q  [B,256,N]
__device__ float g_bufD[33554432]; // split-K partials, later ctx_up [B,512,N]
__device__ float g_context[1048576];  // [B,512,512]
__device__ float g_small[1572864];    // c1 / kmat / v : each [B,256,512]

// ---------------------------------------------------------------------------
// Softmax over rows of length 16384 (row resident in smem).
// grid = B*C rows, 256 threads, 64KB dynamic smem.
// ---------------------------------------------------------------------------
__global__ void softmax_rows16k(const float* __restrict__ x,
                                float* __restrict__ out) {
    extern __shared__ float srow[];        // 16384 floats
    __shared__ float red[256];
    const int NC = NDIM;
    size_t row = blockIdx.x;
    const float* xr = x + row * (size_t)NC;
    float* outr = out + row * (size_t)NC;
    int tid = threadIdx.x;

    float m = -3.4e38f;
    for (int i = tid * 4; i < NC; i += 1024) {
        float4 v = *(const float4*)&xr[i];
        *(float4*)&srow[i] = v;
        m = fmaxf(m, fmaxf(fmaxf(v.x, v.y), fmaxf(v.z, v.w)));
    }
    red[tid] = m;
    __syncthreads();
    for (int s = 128; s > 0; s >>= 1) {
        if (tid < s) red[tid] = fmaxf(red[tid], red[tid + s]);
        __syncthreads();
    }
    m = red[0];
    __syncthreads();

    float sum = 0.f;
    for (int i = tid * 4; i < NC; i += 1024) {
        float4 v = *(float4*)&srow[i];
        v.x = __expf(v.x - m); v.y = __expf(v.y - m);
        v.z = __expf(v.z - m); v.w = __expf(v.w - m);
        *(float4*)&srow[i] = v;
        sum += v.x + v.y + v.z + v.w;
    }
    red[tid] = sum;
    __syncthreads();
    for (int s = 128; s > 0; s >>= 1) {
        if (tid < s) red[tid] += red[tid + s];
        __syncthreads();
    }
    float inv = 1.f / red[0];

    for (int i = tid * 4; i < NC; i += 1024) {
        float4 v = *(float4*)&srow[i];
        v.x *= inv; v.y *= inv; v.z *= inv; v.w *= inv;
        *(float4*)&outr[i] = v;
    }
}

// ---------------------------------------------------------------------------
// Softmax over rows of length 512 (in-place). grid = B*N rows, 128 threads.
// ---------------------------------------------------------------------------
__global__ void softmax_k512(float* __restrict__ sim) {
    __shared__ float redm[4];
    __shared__ float reds[4];
    size_t row = blockIdx.x;
    float* r = sim + row * 512;
    int tid = threadIdx.x;

    float4 v = *(float4*)&r[tid * 4];
    float m = fmaxf(fmaxf(v.x, v.y), fmaxf(v.z, v.w));
    #pragma unroll
    for (int o = 16; o > 0; o >>= 1)
        m = fmaxf(m, __shfl_xor_sync(0xffffffffu, m, o));
    if ((tid & 31) == 0) redm[tid >> 5] = m;
    __syncthreads();
    m = fmaxf(fmaxf(redm[0], redm[1]), fmaxf(redm[2], redm[3]));

    float e0 = __expf(v.x - m), e1 = __expf(v.y - m);
    float e2 = __expf(v.z - m), e3 = __expf(v.w - m);
    float s = e0 + e1 + e2 + e3;
    #pragma unroll
    for (int o = 16; o > 0; o >>= 1)
        s += __shfl_xor_sync(0xffffffffu, s, o);
    if ((tid & 31) == 0) reds[tid >> 5] = s;
    __syncthreads();
    float inv = 1.f / (reds[0] + reds[1] + reds[2] + reds[3]);

    float4 o4 = make_float4(e0 * inv, e1 * inv, e2 * inv, e3 * inv);
    *(float4*)&r[tid * 4] = o4;
}

// ---------------------------------------------------------------------------
// Generic batched tiled GEMM: C[m,n] = act( alpha * sum_k opA(m,k)*opB(k,n) + bias[m] )
//   TA: A stored [K x M] (lda>=M) else [M x K] (lda>=K)
//   TB: B stored [N x K] (ldb>=K) else [K x N] (ldb>=N)
//   CONCAT (TB=false only): rows k >= ksplitB come from B2 (same ldb).
//   gridDim.z = batch * nsplit (split-K: partials written to C + z*sCz).
// Requires: M%128==0, N%128==0, K%8==0, lda/ldb/ldc %4==0.
// 128x128x8 tile, 256 threads, 8x8 microtile.
// ---------------------------------------------------------------------------
template <bool TA, bool TB, bool CONCAT>
__global__ void __launch_bounds__(256)
gemm_kernel(const float* __restrict__ A, size_t sA, int lda,
            const float* __restrict__ B, size_t sB, int ldb,
            const float* __restrict__ B2, size_t sB2, int ksplitB,
            float* __restrict__ C, size_t sCz, int ldc,
            const float* __restrict__ bias, float alpha, int doRelu,
            int M, int N, int K, int nsplit) {
    __shared__ float As[8][132];
    __shared__ float Bs[8][132];

    int z = blockIdx.z;
    int b = z / nsplit;
    int sidx = z - b * nsplit;
    int kchunk = K / nsplit;
    int kbeg = sidx * kchunk;
    int kend = kbeg + kchunk;

    const float* Ab = A + (size_t)b * sA;
    const float* Bb = B + (size_t)b * sB;
    const float* B2b = CONCAT ? (B2 + (size_t)b * sB2) : (const float*)nullptr;
    float* Cb = C + (size_t)z * sCz;

    int m0 = blockIdx.y * 128;
    int n0 = blockIdx.x * 128;
    int tid = threadIdx.x;
    int tx = tid & 15;
    int ty = tid >> 4;

    float acc[8][8];
    #pragma unroll
    for (int i = 0; i < 8; i++)
        #pragma unroll
        for (int j = 0; j < 8; j++) acc[i][j] = 0.f;

    for (int k0 = kbeg; k0 < kend; k0 += 8) {
        // ---- load A tile -> As[k][m]
        if (TA) {
            int kk = tid >> 5;
            int mm = (tid & 31) * 4;
            float4 v = *(const float4*)&Ab[(size_t)(k0 + kk) * lda + m0 + mm];
            *(float4*)&As[kk][mm] = v;
        } else {
            int mm = tid >> 1;
            int kk = (tid & 1) * 4;
            float4 v = *(const float4*)&Ab[(size_t)(m0 + mm) * lda + k0 + kk];
            As[kk + 0][mm] = v.x; As[kk + 1][mm] = v.y;
            As[kk + 2][mm] = v.z; As[kk + 3][mm] = v.w;
        }
        // ---- load B tile -> Bs[k][n]
        if (TB) {
            int nn = tid >> 1;
            int kk = (tid & 1) * 4;
            float4 v = *(const float4*)&Bb[(size_t)(n0 + nn) * ldb + k0 + kk];
            Bs[kk + 0][nn] = v.x; Bs[kk + 1][nn] = v.y;
            Bs[kk + 2][nn] = v.z; Bs[kk + 3][nn] = v.w;
        } else {
            int kk = tid >> 5;
            int nn = (tid & 31) * 4;
            int kr = k0 + kk;
            float4 v;
            if (CONCAT && kr >= ksplitB)
                v = *(const float4*)&B2b[(size_t)(kr - ksplitB) * ldb + n0 + nn];
            else
                v = *(const float4*)&Bb[(size_t)kr * ldb + n0 + nn];
            *(float4*)&Bs[kk][nn] = v;
        }
        __syncthreads();

        #pragma unroll
        for (int kk = 0; kk < 8; kk++) {
            float af[8], bf[8];
            *(float4*)&af[0] = *(float4*)&As[kk][ty * 8];
            *(float4*)&af[4] = *(float4*)&As[kk][ty * 8 + 4];
            *(float4*)&bf[0] = *(float4*)&Bs[kk][tx * 8];
            *(float4*)&bf[4] = *(float4*)&Bs[kk][tx * 8 + 4];
            #pragma unroll
            for (int i = 0; i < 8; i++)
                #pragma unroll
                for (int j = 0; j < 8; j++)
                    acc[i][j] += af[i] * bf[j];
        }
        __syncthreads();
    }

    // ---- epilogue: alpha, bias, relu, store
    #pragma unroll
    for (int i = 0; i < 8; i++) {
        int m = m0 + ty * 8 + i;
        float bv = bias ? bias[m] : 0.f;
        #pragma unroll
        for (int j = 0; j < 8; j += 4) {
            float4 o;
            o.x = acc[i][j + 0] * alpha + bv;
            o.y = acc[i][j + 1] * alpha + bv;
            o.z = acc[i][j + 2] * alpha + bv;
            o.w = acc[i][j + 3] * alpha + bv;
            if (doRelu) {
                o.x = fmaxf(o.x, 0.f); o.y = fmaxf(o.y, 0.f);
                o.z = fmaxf(o.z, 0.f); o.w = fmaxf(o.w, 0.f);
            }
            *(float4*)&Cb[(size_t)m * ldc + n0 + tx * 8 + j] = o;
        }
    }
}

// Sum split-K partials: out[b*per + r] = sum_s in[(b*nsplit+s)*per + r]
__global__ void reduce_split(const float* __restrict__ in,
                             float* __restrict__ out, int per, int nsplit,
                             size_t total) {
    size_t i = (size_t)blockIdx.x * blockDim.x + threadIdx.x;
    if (i >= total) return;
    size_t b = i / per;
    size_t r = i - b * per;
    const float* src = in + b * (size_t)nsplit * per + r;
    float s = 0.f;
    for (int ss = 0; ss < nsplit; ss++) s += src[(size_t)ss * per];
    out[i] = s;
}

// ---------------------------------------------------------------------------
extern "C" void kernel_launch(void* const* d_in, const int* in_sizes, int n_in,
                              void* d_out, int out_size) {
    (void)in_sizes; (void)n_in; (void)out_size;
    const float* feat = (const float*)d_in[0];
    // d_in[1] = prob (dead input)
    const float* wp1 = (const float*)d_in[2];
    const float* bp1 = (const float*)d_in[3];
    const float* wp2 = (const float*)d_in[4];
    const float* bp2 = (const float*)d_in[5];
    const float* wo1 = (const float*)d_in[6];
    const float* bo1 = (const float*)d_in[7];
    const float* wo2 = (const float*)d_in[8];
    const float* bo2 = (const float*)d_in[9];
    const float* wd  = (const float*)d_in[10];
    const float* bd  = (const float*)d_in[11];
    const float* wu  = (const float*)d_in[12];
    const float* bu  = (const float*)d_in[13];
    const float* wout = (const float*)d_in[14];
    const float* bout = (const float*)d_in[15];
    float* outp = (float*)d_out;

    float *bufA, *bufB, *bufC, *bufD, *ctxp, *smallp;
    cudaGetSymbolAddress((void**)&bufA, g_bufA);
    cudaGetSymbolAddress((void**)&bufB, g_bufB);
    cudaGetSymbolAddress((void**)&bufC, g_bufC);
    cudaGetSymbolAddress((void**)&bufD, g_bufD);
    cudaGetSymbolAddress((void**)&ctxp, g_context);
    cudaGetSymbolAddress((void**)&smallp, g_small);
    float* c1p = smallp;                 // [B,256,512]
    float* kmp = smallp + 524288;        // [B,256,512]
    float* vp  = smallp + 1048576;       // [B,256,512]

    const size_t sBN = (size_t)CDIM * NDIM;      // 512*16384 batch stride
    const size_t sKN = (size_t)KEYD * NDIM;      // 256*16384
    const size_t sCC = (size_t)CDIM * CDIM;      // 512*512
    const size_t sKC = (size_t)KEYD * CDIM;      // 256*512

    cudaFuncSetAttribute(softmax_rows16k,
                         cudaFuncAttributeMaxDynamicSharedMemorySize, 65536);

    // 1) pw = softmax(x, axis=-1)  -> bufA
    softmax_rows16k<<<BATCH * CDIM, 256, 65536>>>(feat, bufA);

    // 2) context partials = X * PW^T (split-K=16)  -> bufD
    {
        dim3 g(CDIM / 128, CDIM / 128, BATCH * 16);
        gemm_kernel<false, true, false><<<g, 256>>>(
            feat, sBN, NDIM, bufA, sBN, NDIM, nullptr, 0, 0,
            bufD, sCC, CDIM, nullptr, 1.f, 0, CDIM, CDIM, NDIM, 16);
    }
    // 3) reduce split-K -> g_context
    {
        size_t total = (size_t)BATCH * sCC;
        reduce_split<<<(unsigned)((total + 255) / 256), 256>>>(
            bufD, ctxp, (int)sCC, 16, total);
    }
    // 4) t1 = relu(wp1 @ x + bp1)  -> bufB
    {
        dim3 g(NDIM / 128, KEYD / 128, BATCH);
        gemm_kernel<false, false, false><<<g, 256>>>(
            wp1, 0, CDIM, feat, sBN, NDIM, nullptr, 0, 0,
            bufB, sKN, NDIM, bp1, 1.f, 1, KEYD, NDIM, CDIM, 1);
    }
    // 5) q = relu(wp2 @ t1 + bp2)  -> bufC
    {
        dim3 g(NDIM / 128, KEYD / 128, BATCH);
        gemm_kernel<false, false, false><<<g, 256>>>(
            wp2, 0, KEYD, bufB, sKN, NDIM, nullptr, 0, 0,
            bufC, sKN, NDIM, bp2, 1.f, 1, KEYD, NDIM, KEYD, 1);
    }
    // 6) c1 = relu(wo1 @ context + bo1)  -> c1p
    {
        dim3 g(CDIM / 128, KEYD / 128, BATCH);
        gemm_kernel<false, false, false><<<g, 256>>>(
            wo1, 0, CDIM, ctxp, sCC, CDIM, nullptr, 0, 0,
            c1p, sKC, CDIM, bo1, 1.f, 1, KEYD, CDIM, CDIM, 1);
    }
    // 7) kmat = relu(wo2 @ c1 + bo2)  -> kmp
    {
        dim3 g(CDIM / 128, KEYD / 128, BATCH);
        gemm_kernel<false, false, false><<<g, 256>>>(
            wo2, 0, KEYD, c1p, sKC, CDIM, nullptr, 0, 0,
            kmp, sKC, CDIM, bo2, 1.f, 1, KEYD, CDIM, KEYD, 1);
    }
    // 8) v = relu(wd @ context + bd)  -> vp
    {
        dim3 g(CDIM / 128, KEYD / 128, BATCH);
        gemm_kernel<false, false, false><<<g, 256>>>(
            wd, 0, CDIM, ctxp, sCC, CDIM, nullptr, 0, 0,
            vp, sKC, CDIM, bd, 1.f, 1, KEYD, CDIM, CDIM, 1);
    }
    // 9) sim = (Q^T K) * KEY^-0.5   -> bufA  [B, N, 512]
    {
        dim3 g(CDIM / 128, NDIM / 128, BATCH);
        gemm_kernel<true, false, false><<<g, 256>>>(
            bufC, sKN, NDIM, kmp, sKC, CDIM, nullptr, 0, 0,
            bufA, (size_t)NDIM * CDIM, CDIM, nullptr, 0.0625f, 0,
            NDIM, CDIM, KEYD, 1);
    }
    // 10) softmax over K=512 (in place)
    softmax_k512<<<BATCH * NDIM, 128>>>(bufA);

    // 11) attn ctx = V @ SIM^T  -> bufB  [B,256,N]
    {
        dim3 g(NDIM / 128, KEYD / 128, BATCH);
        gemm_kernel<false, true, false><<<g, 256>>>(
            vp, sKC, CDIM, bufA, (size_t)NDIM * CDIM, CDIM, nullptr, 0, 0,
            bufB, sKN, NDIM, nullptr, 1.f, 0, KEYD, NDIM, CDIM, 1);
    }
    // 12) ctx_up = relu(wu @ attn_ctx + bu)  -> bufD  [B,512,N]
    {
        dim3 g(NDIM / 128, CDIM / 128, BATCH);
        gemm_kernel<false, false, false><<<g, 256>>>(
            wu, 0, KEYD, bufB, sKN, NDIM, nullptr, 0, 0,
            bufD, sBN, NDIM, bu, 1.f, 1, CDIM, NDIM, KEYD, 1);
    }
    // 13) out = relu(wout @ concat(ctx_up, x) + bout)  -> d_out
    {
        dim3 g(NDIM / 128, CDIM / 128, BATCH);
        gemm_kernel<false, false, true><<<g, 256>>>(
            wout, 0, 2 * CDIM, bufD, sBN, NDIM, feat, sBN, CDIM,
            outp, sBN, NDIM, bout, 1.f, 1, CDIM, NDIM, 2 * CDIM, 1);
    }
}

// round 2
// speedup vs baseline: 2.8352x; 2.8352x over previous
#include <cuda_runtime.h>
#include <cuda_bf16.h>
#include <cstdint>
#include <cstddef>

// ---------------------------------------------------------------------------
// OCR head on GB300 — Round 2: all GEMMs moved to TF32 tensor cores
// (mma.sync.aligned.m16n8k8.row.col.f32.tf32.tf32.f32), fp32 accumulate.
// Tile 128x128x16, 8 warps, warp tile 64x32, conflict-free padded smem,
// gmem->reg prefetch pipelined over the MMA stage. Fused bias+ReLU epilogue,
// split-K for the K=16384 context GEMM. Softmaxes unchanged (memory-trivial).
// ---------------------------------------------------------------------------

#define BATCH 4
#define CDIM 512
#define NDIM 16384
#define KEYD 256

// Scratch pools (reused across stages):
__device__ float g_bufA[33554432]; // pw [B,512,N], later sim [B,N,512]
__device__ float g_bufB[16777216]; // t1 [B,256,N], later attn ctx [B,256,N]
__device__ float g_bufC[16777216]; // q  [B,256,N]
__device__ float g_bufD[33554432]; // split-K partials, later ctx_up [B,512,N]
__device__ float g_context[1048576];  // [B,512,512]
__device__ float g_small[1572864];    // c1 / kmat / v : each [B,256,512]

// ---------------------------------------------------------------------------
__global__ void softmax_rows16k(const float* __restrict__ x,
                                float* __restrict__ out) {
    extern __shared__ float srow[];        // 16384 floats
    __shared__ float red[256];
    const int NC = NDIM;
    size_t row = blockIdx.x;
    const float* xr = x + row * (size_t)NC;
    float* outr = out + row * (size_t)NC;
    int tid = threadIdx.x;

    float m = -3.4e38f;
    for (int i = tid * 4; i < NC; i += 1024) {
        float4 v = *(const float4*)&xr[i];
        *(float4*)&srow[i] = v;
        m = fmaxf(m, fmaxf(fmaxf(v.x, v.y), fmaxf(v.z, v.w)));
    }
    red[tid] = m;
    __syncthreads();
    for (int s = 128; s > 0; s >>= 1) {
        if (tid < s) red[tid] = fmaxf(red[tid], red[tid + s]);
        __syncthreads();
    }
    m = red[0];
    __syncthreads();

    float sum = 0.f;
    for (int i = tid * 4; i < NC; i += 1024) {
        float4 v = *(float4*)&srow[i];
        v.x = __expf(v.x - m); v.y = __expf(v.y - m);
        v.z = __expf(v.z - m); v.w = __expf(v.w - m);
        *(float4*)&srow[i] = v;
        sum += v.x + v.y + v.z + v.w;
    }
    red[tid] = sum;
    __syncthreads();
    for (int s = 128; s > 0; s >>= 1) {
        if (tid < s) red[tid] += red[tid + s];
        __syncthreads();
    }
    float inv = 1.f / red[0];

    for (int i = tid * 4; i < NC; i += 1024) {
        float4 v = *(float4*)&srow[i];
        v.x *= inv; v.y *= inv; v.z *= inv; v.w *= inv;
        *(float4*)&outr[i] = v;
    }
}

// ---------------------------------------------------------------------------
__global__ void softmax_k512(float* __restrict__ sim) {
    __shared__ float redm[4];
    __shared__ float reds[4];
    size_t row = blockIdx.x;
    float* r = sim + row * 512;
    int tid = threadIdx.x;

    float4 v = *(float4*)&r[tid * 4];
    float m = fmaxf(fmaxf(v.x, v.y), fmaxf(v.z, v.w));
    #pragma unroll
    for (int o = 16; o > 0; o >>= 1)
        m = fmaxf(m, __shfl_xor_sync(0xffffffffu, m, o));
    if ((tid & 31) == 0) redm[tid >> 5] = m;
    __syncthreads();
    m = fmaxf(fmaxf(redm[0], redm[1]), fmaxf(redm[2], redm[3]));

    float e0 = __expf(v.x - m), e1 = __expf(v.y - m);
    float e2 = __expf(v.z - m), e3 = __expf(v.w - m);
    float s = e0 + e1 + e2 + e3;
    #pragma unroll
    for (int o = 16; o > 0; o >>= 1)
        s += __shfl_xor_sync(0xffffffffu, s, o);
    if ((tid & 31) == 0) reds[tid >> 5] = s;
    __syncthreads();
    float inv = 1.f / (reds[0] + reds[1] + reds[2] + reds[3]);

    float4 o4 = make_float4(e0 * inv, e1 * inv, e2 * inv, e3 * inv);
    *(float4*)&r[tid * 4] = o4;
}

// ---------------------------------------------------------------------------
__device__ __forceinline__ uint32_t f2tf32(float f) {
    uint32_t u;
    asm("cvt.rna.tf32.f32 %0, %1;" : "=r"(u) : "f"(f));
    return u;
}

__device__ __forceinline__ void mma_tf32(float c[4], const uint32_t a[4],
                                         const uint32_t b[2]) {
    asm volatile(
        "mma.sync.aligned.m16n8k8.row.col.f32.tf32.tf32.f32 "
        "{%0,%1,%2,%3}, {%4,%5,%6,%7}, {%8,%9}, {%0,%1,%2,%3};"
        : "+f"(c[0]), "+f"(c[1]), "+f"(c[2]), "+f"(c[3])
        : "r"(a[0]), "r"(a[1]), "r"(a[2]), "r"(a[3]), "r"(b[0]), "r"(b[1]));
}

// ---------------------------------------------------------------------------
// TF32 batched tiled GEMM: C[m,n] = act(alpha * sum_k opA(m,k)*opB(k,n) + bias[m])
//   TA: A stored [K x M] (lda) else [M x K] (lda)
//   TB: B stored [N x K] (ldb) else [K x N] (ldb)
//   CONCAT (TB=false only): rows k >= ksplitB come from B2 (same ldb).
//   gridDim.z = batch * nsplit (split-K partials at C + z*sCz).
// Requires M%128==0, N%128==0, K%16==0. 128x128x16 tile, 256 thr, 8 warps.
// ---------------------------------------------------------------------------
template <bool TA, bool TB, bool CONCAT>
__global__ void __launch_bounds__(256, 2)
gemm_tf32(const float* __restrict__ A, size_t sA, int lda,
          const float* __restrict__ B, size_t sB, int ldb,
          const float* __restrict__ B2, size_t sB2, int ksplitB,
          float* __restrict__ C, size_t sCz, int ldc,
          const float* __restrict__ bias, float alpha, int doRelu,
          int M, int N, int K, int nsplit) {
    __shared__ __align__(16) uint32_t As[16][136];
    __shared__ __align__(16) uint32_t Bs[16][136];

    int z = blockIdx.z;
    int b = z / nsplit;
    int sidx = z - b * nsplit;
    int kchunk = K / nsplit;
    int kbeg = sidx * kchunk;
    int kend = kbeg + kchunk;

    const float* Ab = A + (size_t)b * sA;
    const float* Bb = B + (size_t)b * sB;
    const float* B2b = CONCAT ? (B2 + (size_t)b * sB2) : (const float*)nullptr;
    float* Cb = C + (size_t)z * sCz;

    int m0 = blockIdx.y * 128;
    int n0 = blockIdx.x * 128;
    int tid = threadIdx.x;
    int warp = tid >> 5, lane = tid & 31;
    int g = lane >> 2, r = lane & 3;
    int wm = warp & 1, wn = warp >> 1;
    int warp_m0 = wm * 64, warp_n0 = wn * 32;

    float acc[4][4][4];
    #pragma unroll
    for (int i = 0; i < 4; i++)
        #pragma unroll
        for (int j = 0; j < 4; j++)
            #pragma unroll
            for (int e = 0; e < 4; e++) acc[i][j][e] = 0.f;

    float4 stA[2], stB[2];

    // ---- gmem load of one 128x16 A tile + 16x128 B tile into registers
    auto load_tiles = [&](int k0) {
        if (TA) {
            // A stored [K, M]: rows of 128 m, vectorized along m
            #pragma unroll
            for (int i = 0; i < 2; i++) {
                int kk = (tid >> 5) + i * 8;
                int mm = (tid & 31) * 4;
                stA[i] = *(const float4*)&Ab[(size_t)(k0 + kk) * lda + m0 + mm];
            }
        } else {
            // A stored [M, K]: vectorized along k
            int mA = tid >> 1;
            int kA = (tid & 1) * 8;
            const float* p = &Ab[(size_t)(m0 + mA) * lda + k0 + kA];
            stA[0] = *(const float4*)p;
            stA[1] = *(const float4*)(p + 4);
        }
        if (TB) {
            // B stored [N, K]: vectorized along k
            int nB = tid >> 1;
            int kB = (tid & 1) * 8;
            const float* p = &Bb[(size_t)(n0 + nB) * ldb + k0 + kB];
            stB[0] = *(const float4*)p;
            stB[1] = *(const float4*)(p + 4);
        } else {
            // B stored [K, N]: vectorized along n
            #pragma unroll
            for (int i = 0; i < 2; i++) {
                int kk = (tid >> 5) + i * 8;
                int nn = (tid & 31) * 4;
                int kr = k0 + kk;
                if (CONCAT && kr >= ksplitB)
                    stB[i] = *(const float4*)&B2b[(size_t)(kr - ksplitB) * ldb + n0 + nn];
                else
                    stB[i] = *(const float4*)&Bb[(size_t)kr * ldb + n0 + nn];
            }
        }
    };

    auto store_tiles = [&]() {
        if (TA) {
            #pragma unroll
            for (int i = 0; i < 2; i++) {
                int kk = (tid >> 5) + i * 8;
                int mm = (tid & 31) * 4;
                uint4 u;
                u.x = f2tf32(stA[i].x); u.y = f2tf32(stA[i].y);
                u.z = f2tf32(stA[i].z); u.w = f2tf32(stA[i].w);
                *(uint4*)&As[kk][mm] = u;
            }
        } else {
            int mA = tid >> 1;
            int kA = (tid & 1) * 8;
            As[kA + 0][mA] = f2tf32(stA[0].x);
            As[kA + 1][mA] = f2tf32(stA[0].y);
            As[kA + 2][mA] = f2tf32(stA[0].z);
            As[kA + 3][mA] = f2tf32(stA[0].w);
            As[kA + 4][mA] = f2tf32(stA[1].x);
            As[kA + 5][mA] = f2tf32(stA[1].y);
            As[kA + 6][mA] = f2tf32(stA[1].z);
            As[kA + 7][mA] = f2tf32(stA[1].w);
        }
        if (TB) {
            int nB = tid >> 1;
            int kB = (tid & 1) * 8;
            Bs[kB + 0][nB] = f2tf32(stB[0].x);
            Bs[kB + 1][nB] = f2tf32(stB[0].y);
            Bs[kB + 2][nB] = f2tf32(stB[0].z);
            Bs[kB + 3][nB] = f2tf32(stB[0].w);
            Bs[kB + 4][nB] = f2tf32(stB[1].x);
            Bs[kB + 5][nB] = f2tf32(stB[1].y);
            Bs[kB + 6][nB] = f2tf32(stB[1].z);
            Bs[kB + 7][nB] = f2tf32(stB[1].w);
        } else {
            #pragma unroll
            for (int i = 0; i < 2; i++) {
                int kk = (tid >> 5) + i * 8;
                int nn = (tid & 31) * 4;
                uint4 u;
                u.x = f2tf32(stB[i].x); u.y = f2tf32(stB[i].y);
                u.z = f2tf32(stB[i].z); u.w = f2tf32(stB[i].w);
                *(uint4*)&Bs[kk][nn] = u;
            }
        }
    };

    load_tiles(kbeg);

    for (int k0 = kbeg; k0 < kend; k0 += 16) {
        store_tiles();
        __syncthreads();
        bool more = (k0 + 16) < kend;
        if (more) load_tiles(k0 + 16);  // overlap LDG with MMA below

        #pragma unroll
        for (int ks = 0; ks < 16; ks += 8) {
            uint32_t af[4][4], bf[4][2];
            #pragma unroll
            for (int i = 0; i < 4; i++) {
                int mb = warp_m0 + i * 16 + g;
                af[i][0] = As[ks + r][mb];
                af[i][1] = As[ks + r][mb + 8];
                af[i][2] = As[ks + r + 4][mb];
                af[i][3] = As[ks + r + 4][mb + 8];
            }
            #pragma unroll
            for (int j = 0; j < 4; j++) {
                int nb = warp_n0 + j * 8 + g;
                bf[j][0] = Bs[ks + r][nb];
                bf[j][1] = Bs[ks + r + 4][nb];
            }
            #pragma unroll
            for (int i = 0; i < 4; i++)
                #pragma unroll
                for (int j = 0; j < 4; j++)
                    mma_tf32(acc[i][j], af[i], bf[j]);
        }
        __syncthreads();
    }

    // ---- epilogue: alpha, bias, relu, store (float2 per c-pair)
    #pragma unroll
    for (int i = 0; i < 4; i++) {
        int m = m0 + warp_m0 + i * 16 + g;
        float bv0 = bias ? bias[m] : 0.f;
        float bv8 = bias ? bias[m + 8] : 0.f;
        #pragma unroll
        for (int j = 0; j < 4; j++) {
            int n = n0 + warp_n0 + j * 8 + 2 * r;
            float2 lo, hi;
            lo.x = acc[i][j][0] * alpha + bv0;
            lo.y = acc[i][j][1] * alpha + bv0;
            hi.x = acc[i][j][2] * alpha + bv8;
            hi.y = acc[i][j][3] * alpha + bv8;
            if (doRelu) {
                lo.x = fmaxf(lo.x, 0.f); lo.y = fmaxf(lo.y, 0.f);
                hi.x = fmaxf(hi.x, 0.f); hi.y = fmaxf(hi.y, 0.f);
            }
            *(float2*)&Cb[(size_t)m * ldc + n] = lo;
            *(float2*)&Cb[(size_t)(m + 8) * ldc + n] = hi;
        }
    }
}

// Sum split-K partials
__global__ void reduce_split(const float* __restrict__ in,
                             float* __restrict__ out, int per, int nsplit,
                             size_t total) {
    size_t i = (size_t)blockIdx.x * blockDim.x + threadIdx.x;
    if (i >= total) return;
    size_t b = i / per;
    size_t r = i - b * per;
    const float* src = in + b * (size_t)nsplit * per + r;
    float s = 0.f;
    for (int ss = 0; ss < nsplit; ss++) s += src[(size_t)ss * per];
    out[i] = s;
}

// ---------------------------------------------------------------------------
extern "C" void kernel_launch(void* const* d_in, const int* in_sizes, int n_in,
                              void* d_out, int out_size) {
    (void)in_sizes; (void)n_in; (void)out_size;
    const float* feat = (const float*)d_in[0];
    // d_in[1] = prob (dead input)
    const float* wp1 = (const float*)d_in[2];
    const float* bp1 = (const float*)d_in[3];
    const float* wp2 = (const float*)d_in[4];
    const float* bp2 = (const float*)d_in[5];
    const float* wo1 = (const float*)d_in[6];
    const float* bo1 = (const float*)d_in[7];
    const float* wo2 = (const float*)d_in[8];
    const float* bo2 = (const float*)d_in[9];
    const float* wd  = (const float*)d_in[10];
    const float* bd  = (const float*)d_in[11];
    const float* wu  = (const float*)d_in[12];
    const float* bu  = (const float*)d_in[13];
    const float* wout = (const float*)d_in[14];
    const float* bout = (const float*)d_in[15];
    float* outp = (float*)d_out;

    float *bufA, *bufB, *bufC, *bufD, *ctxp, *smallp;
    cudaGetSymbolAddress((void**)&bufA, g_bufA);
    cudaGetSymbolAddress((void**)&bufB, g_bufB);
    cudaGetSymbolAddress((void**)&bufC, g_bufC);
    cudaGetSymbolAddress((void**)&bufD, g_bufD);
    cudaGetSymbolAddress((void**)&ctxp, g_context);
    cudaGetSymbolAddress((void**)&smallp, g_small);
    float* c1p = smallp;                 // [B,256,512]
    float* kmp = smallp + 524288;        // [B,256,512]
    float* vp  = smallp + 1048576;       // [B,256,512]

    const size_t sBN = (size_t)CDIM * NDIM;
    const size_t sKN = (size_t)KEYD * NDIM;
    const size_t sCC = (size_t)CDIM * CDIM;
    const size_t sKC = (size_t)KEYD * CDIM;

    cudaFuncSetAttribute(softmax_rows16k,
                         cudaFuncAttributeMaxDynamicSharedMemorySize, 65536);

    // 1) pw = softmax(x, axis=-1)  -> bufA
    softmax_rows16k<<<BATCH * CDIM, 256, 65536>>>(feat, bufA);

    // 2) context partials = X * PW^T (split-K=16)  -> bufD
    {
        dim3 g(CDIM / 128, CDIM / 128, BATCH * 16);
        gemm_tf32<false, true, false><<<g, 256>>>(
            feat, sBN, NDIM, bufA, sBN, NDIM, nullptr, 0, 0,
            bufD, sCC, CDIM, nullptr, 1.f, 0, CDIM, CDIM, NDIM, 16);
    }
    // 3) reduce split-K -> g_context
    {
        size_t total = (size_t)BATCH * sCC;
        reduce_split<<<(unsigned)((total + 255) / 256), 256>>>(
            bufD, ctxp, (int)sCC, 16, total);
    }
    // 4) t1 = relu(wp1 @ x + bp1)  -> bufB
    {
        dim3 g(NDIM / 128, KEYD / 128, BATCH);
        gemm_tf32<false, false, false><<<g, 256>>>(
            wp1, 0, CDIM, feat, sBN, NDIM, nullptr, 0, 0,
            bufB, sKN, NDIM, bp1, 1.f, 1, KEYD, NDIM, CDIM, 1);
    }
    // 5) q = relu(wp2 @ t1 + bp2)  -> bufC
    {
        dim3 g(NDIM / 128, KEYD / 128, BATCH);
        gemm_tf32<false, false, false><<<g, 256>>>(
            wp2, 0, KEYD, bufB, sKN, NDIM, nullptr, 0, 0,
            bufC, sKN, NDIM, bp2, 1.f, 1, KEYD, NDIM, KEYD, 1);
    }
    // 6) c1 = relu(wo1 @ context + bo1)  -> c1p
    {
        dim3 g(CDIM / 128, KEYD / 128, BATCH);
        gemm_tf32<false, false, false><<<g, 256>>>(
            wo1, 0, CDIM, ctxp, sCC, CDIM, nullptr, 0, 0,
            c1p, sKC, CDIM, bo1, 1.f, 1, KEYD, CDIM, CDIM, 1);
    }
    // 7) kmat = relu(wo2 @ c1 + bo2)  -> kmp
    {
        dim3 g(CDIM / 128, KEYD / 128, BATCH);
        gemm_tf32<false, false, false><<<g, 256>>>(
            wo2, 0, KEYD, c1p, sKC, CDIM, nullptr, 0, 0,
            kmp, sKC, CDIM, bo2, 1.f, 1, KEYD, CDIM, KEYD, 1);
    }
    // 8) v = relu(wd @ context + bd)  -> vp
    {
        dim3 g(CDIM / 128, KEYD / 128, BATCH);
        gemm_tf32<false, false, false><<<g, 256>>>(
            wd, 0, CDIM, ctxp, sCC, CDIM, nullptr, 0, 0,
            vp, sKC, CDIM, bd, 1.f, 1, KEYD, CDIM, CDIM, 1);
    }
    // 9) sim = (Q^T K) * KEY^-0.5   -> bufA  [B, N, 512]
    {
        dim3 g(CDIM / 128, NDIM / 128, BATCH);
        gemm_tf32<true, false, false><<<g, 256>>>(
            bufC, sKN, NDIM, kmp, sKC, CDIM, nullptr, 0, 0,
            bufA, (size_t)NDIM * CDIM, CDIM, nullptr, 0.0625f, 0,
            NDIM, CDIM, KEYD, 1);
    }
    // 10) softmax over K=512 (in place)
    softmax_k512<<<BATCH * NDIM, 128>>>(bufA);

    // 11) attn ctx = V @ SIM^T  -> bufB  [B,256,N]
    {
        dim3 g(NDIM / 128, KEYD / 128, BATCH);
        gemm_tf32<false, true, false><<<g, 256>>>(
            vp, sKC, CDIM, bufA, (size_t)NDIM * CDIM, CDIM, nullptr, 0, 0,
            bufB, sKN, NDIM, nullptr, 1.f, 0, KEYD, NDIM, CDIM, 1);
    }
    // 12) ctx_up = relu(wu @ attn_ctx + bu)  -> bufD  [B,512,N]
    {
        dim3 g(NDIM / 128, CDIM / 128, BATCH);
        gemm_tf32<false, false, false><<<g, 256>>>(
            wu, 0, KEYD, bufB, sKN, NDIM, nullptr, 0, 0,
            bufD, sBN, NDIM, bu, 1.f, 1, CDIM, NDIM, KEYD, 1);
    }
    // 13) out = relu(wout @ concat(ctx_up, x) + bout)  -> d_out
    {
        dim3 g(NDIM / 128, CDIM / 128, BATCH);
        gemm_tf32<false, false, true><<<g, 256>>>(
            wout, 0, 2 * CDIM, bufD, sBN, NDIM, feat, sBN, CDIM,
            outp, sBN, NDIM, bout, 1.f, 1, CDIM, NDIM, 2 * CDIM, 1);
    }
}

// round 4
// speedup vs baseline: 3.2904x; 1.1606x over previous
#include <cuda_runtime.h>
#include <cuda_bf16.h>
#include <cstdint>
#include <cstddef>

// ---------------------------------------------------------------------------
// OCR head on GB300 — Round 4 (Round-3 resubmit after infra failure):
// TF32 mma.sync GEMMs, cp.async double buffering, 128x256x32 CTA tile,
// 64x64 warp tile (8 warps), ldmatrix A fragments, conflict-free pads,
// implicit tf32 truncation (no cvt).
// ---------------------------------------------------------------------------

#define BATCH 4
#define CDIM 512
#define NDIM 16384
#define KEYD 256

__device__ float g_bufA[33554432]; // pw [B,512,N], later sim [B,N,512]
__device__ float g_bufB[16777216]; // t1 [B,256,N], later attn ctx [B,256,N]
__device__ float g_bufC[16777216]; // q  [B,256,N]
__device__ float g_bufD[33554432]; // split-K partials, later ctx_up [B,512,N]
__device__ float g_context[1048576];  // [B,512,512]
__device__ float g_small[1572864];    // c1 / kmat / v : each [B,256,512]

// ---------------------------------------------------------------------------
__global__ void softmax_rows16k(const float* __restrict__ x,
                                float* __restrict__ out) {
    extern __shared__ float srow[];        // 16384 floats
    __shared__ float red[256];
    const int NC = NDIM;
    size_t row = blockIdx.x;
    const float* xr = x + row * (size_t)NC;
    float* outr = out + row * (size_t)NC;
    int tid = threadIdx.x;

    float m = -3.4e38f;
    for (int i = tid * 4; i < NC; i += 1024) {
        float4 v = *(const float4*)&xr[i];
        *(float4*)&srow[i] = v;
        m = fmaxf(m, fmaxf(fmaxf(v.x, v.y), fmaxf(v.z, v.w)));
    }
    red[tid] = m;
    __syncthreads();
    for (int s = 128; s > 0; s >>= 1) {
        if (tid < s) red[tid] = fmaxf(red[tid], red[tid + s]);
        __syncthreads();
    }
    m = red[0];
    __syncthreads();

    float sum = 0.f;
    for (int i = tid * 4; i < NC; i += 1024) {
        float4 v = *(float4*)&srow[i];
        v.x = __expf(v.x - m); v.y = __expf(v.y - m);
        v.z = __expf(v.z - m); v.w = __expf(v.w - m);
        *(float4*)&srow[i] = v;
        sum += v.x + v.y + v.z + v.w;
    }
    red[tid] = sum;
    __syncthreads();
    for (int s = 128; s > 0; s >>= 1) {
        if (tid < s) red[tid] += red[tid + s];
        __syncthreads();
    }
    float inv = 1.f / red[0];

    for (int i = tid * 4; i < NC; i += 1024) {
        float4 v = *(float4*)&srow[i];
        v.x *= inv; v.y *= inv; v.z *= inv; v.w *= inv;
        *(float4*)&outr[i] = v;
    }
}

// ---------------------------------------------------------------------------
__global__ void softmax_k512(float* __restrict__ sim) {
    __shared__ float redm[4];
    __shared__ float reds[4];
    size_t row = blockIdx.x;
    float* r = sim + row * 512;
    int tid = threadIdx.x;

    float4 v = *(float4*)&r[tid * 4];
    float m = fmaxf(fmaxf(v.x, v.y), fmaxf(v.z, v.w));
    #pragma unroll
    for (int o = 16; o > 0; o >>= 1)
        m = fmaxf(m, __shfl_xor_sync(0xffffffffu, m, o));
    if ((tid & 31) == 0) redm[tid >> 5] = m;
    __syncthreads();
    m = fmaxf(fmaxf(redm[0], redm[1]), fmaxf(redm[2], redm[3]));

    float e0 = __expf(v.x - m), e1 = __expf(v.y - m);
    float e2 = __expf(v.z - m), e3 = __expf(v.w - m);
    float s = e0 + e1 + e2 + e3;
    #pragma unroll
    for (int o = 16; o > 0; o >>= 1)
        s += __shfl_xor_sync(0xffffffffu, s, o);
    if ((tid & 31) == 0) reds[tid >> 5] = s;
    __syncthreads();
    float inv = 1.f / (reds[0] + reds[1] + reds[2] + reds[3]);

    float4 o4 = make_float4(e0 * inv, e1 * inv, e2 * inv, e3 * inv);
    *(float4*)&r[tid * 4] = o4;
}

// ---------------------------------------------------------------------------
__device__ __forceinline__ void mma_tf32(float c[4], const uint32_t a[4],
                                         const uint32_t b[2]) {
    asm volatile(
        "mma.sync.aligned.m16n8k8.row.col.f32.tf32.tf32.f32 "
        "{%0,%1,%2,%3}, {%4,%5,%6,%7}, {%8,%9}, {%0,%1,%2,%3};"
        : "+f"(c[0]), "+f"(c[1]), "+f"(c[2]), "+f"(c[3])
        : "r"(a[0]), "r"(a[1]), "r"(a[2]), "r"(a[3]), "r"(b[0]), "r"(b[1]));
}

__device__ __forceinline__ void cp16(uint32_t dst, const float* src) {
    asm volatile("cp.async.cg.shared.global [%0], [%1], 16;\n"
                 :: "r"(dst), "l"(src));
}
__device__ __forceinline__ void cp_commit() {
    asm volatile("cp.async.commit_group;\n" ::: "memory");
}
__device__ __forceinline__ void cp_wait0() {
    asm volatile("cp.async.wait_group 0;\n" ::: "memory");
}
__device__ __forceinline__ void cp_wait_all() {
    asm volatile("cp.async.wait_all;\n" ::: "memory");
}
__device__ __forceinline__ void ldsm_x4(uint32_t& r0, uint32_t& r1,
                                        uint32_t& r2, uint32_t& r3,
                                        uint32_t addr) {
    asm volatile("ldmatrix.sync.aligned.m8n8.x4.shared.b16 {%0,%1,%2,%3}, [%4];"
                 : "=r"(r0), "=r"(r1), "=r"(r2), "=r"(r3) : "r"(addr));
}

// ---------------------------------------------------------------------------
// TF32 batched GEMM: C[m,n] = act(alpha * sum_k opA(m,k)*opB(k,n) + bias[m])
//   TA: A stored [K,M] (lda) else [M,K] ; TB: B stored [N,K] else [K,N].
//   CONCAT (TB=false): k rows >= ksplitB come from B2.
//   gridDim.z = batch*nsplit (split-K partials at C + z*sCz).
// CTA tile 128x256x32, 256 threads, 8 warps (2m x 4n), warp tile 64x64.
// Requires M%128==0, N%256==0, K%32==0.
// ---------------------------------------------------------------------------
template <bool TA, bool TB, bool CONCAT>
__global__ void __launch_bounds__(256, 1)
gemm_tf32(const float* __restrict__ A, size_t sA, int lda,
          const float* __restrict__ B, size_t sB, int ldb,
          const float* __restrict__ B2, size_t sB2, int ksplitB,
          float* __restrict__ C, size_t sCz, int ldc,
          const float* __restrict__ bias, float alpha, int doRelu,
          int M, int N, int K, int nsplit) {
    constexpr int BM = 128, BN = 256, BK = 32;
    constexpr int APAD_T = 136;   // TA=true : As[k][m], pad 128+8
    constexpr int APAD_N = 36;    // TA=false: As[m][k], pad 32+4
    constexpr int BPAD_T = 36;    // TB=true : Bs[n][k], pad 32+4
    constexpr int BPAD_N = 264;   // TB=false: Bs[k][n], pad 256+8
    constexpr int ASZ = TA ? BK * APAD_T : BM * APAD_N;
    constexpr int BSZ = TB ? BN * BPAD_T : BK * BPAD_N;

    extern __shared__ float smem[];
    float* Asm[2] = { smem, smem + ASZ + BSZ };
    float* Bsm[2] = { smem + ASZ, smem + 2 * ASZ + BSZ };

    int z = blockIdx.z;
    int b = z / nsplit;
    int sidx = z - b * nsplit;
    int kchunk = K / nsplit;
    int kbeg = sidx * kchunk;
    int niter = kchunk / BK;

    const float* Ab = A + (size_t)b * sA;
    const float* Bb = B + (size_t)b * sB;
    const float* B2b = CONCAT ? (B2 + (size_t)b * sB2) : (const float*)nullptr;
    float* Cb = C + (size_t)z * sCz;

    int m0 = blockIdx.y * BM;
    int n0 = blockIdx.x * BN;
    int tid = threadIdx.x;
    int warp = tid >> 5, lane = tid & 31;
    int g = lane >> 2, r = lane & 3;
    int wm = warp & 1, wn = warp >> 1;
    int warp_m0 = wm * 64, warp_n0 = wn * 64;

    float acc[4][8][4];
    #pragma unroll
    for (int i = 0; i < 4; i++)
        #pragma unroll
        for (int j = 0; j < 8; j++)
            #pragma unroll
            for (int e = 0; e < 4; e++) acc[i][j][e] = 0.f;

    // ---- async prefetch of one k-slab into stage st
    auto prefetch = [&](int st, int k0) {
        uint32_t abase = (uint32_t)__cvta_generic_to_shared(Asm[st]);
        uint32_t bbase = (uint32_t)__cvta_generic_to_shared(Bsm[st]);
        if (TA) {
            // [K,M] -> Asm[k][m] : 32 rows x 32 chunks
            #pragma unroll
            for (int p = 0; p < 4; p++) {
                int c = tid + p * 256;
                int row = c >> 5, mc = (c & 31) * 4;
                cp16(abase + (row * APAD_T + mc) * 4,
                     &Ab[(size_t)(k0 + row) * lda + m0 + mc]);
            }
        } else {
            // [M,K] -> Asm[m][k] : 128 rows x 8 chunks
            #pragma unroll
            for (int p = 0; p < 4; p++) {
                int c = tid + p * 256;
                int row = c >> 3, kc = (c & 7) * 4;
                cp16(abase + (row * APAD_N + kc) * 4,
                     &Ab[(size_t)(m0 + row) * lda + k0 + kc]);
            }
        }
        if (TB) {
            // [N,K] -> Bsm[n][k] : 256 rows x 8 chunks
            #pragma unroll
            for (int p = 0; p < 8; p++) {
                int c = tid + p * 256;
                int row = c >> 3, kc = (c & 7) * 4;
                cp16(bbase + (row * BPAD_T + kc) * 4,
                     &Bb[(size_t)(n0 + row) * ldb + k0 + kc]);
            }
        } else {
            // [K,N] -> Bsm[k][n] : 32 rows x 64 chunks
            #pragma unroll
            for (int p = 0; p < 8; p++) {
                int c = tid + p * 256;
                int row = c >> 6, nc = (c & 63) * 4;
                int kr = k0 + row;
                const float* src;
                if (CONCAT && kr >= ksplitB)
                    src = &B2b[(size_t)(kr - ksplitB) * ldb + n0 + nc];
                else
                    src = &Bb[(size_t)kr * ldb + n0 + nc];
                cp16(bbase + (row * BPAD_N + nc) * 4, src);
            }
        }
        cp_commit();
    };

    prefetch(0, kbeg);

    for (int it = 0; it < niter; it++) {
        int st = it & 1;
        cp_wait0();
        __syncthreads();
        if (it + 1 < niter) prefetch(st ^ 1, kbeg + (it + 1) * BK);

        const uint32_t* Au = (const uint32_t*)Asm[st];
        const uint32_t* Bu = (const uint32_t*)Bsm[st];
        uint32_t a_ldsm_base = (uint32_t)__cvta_generic_to_shared(Asm[st]);

        #pragma unroll
        for (int ks = 0; ks < BK; ks += 8) {
            uint32_t af[4][4], bf[8][2];
            if (TA) {
                #pragma unroll
                for (int i = 0; i < 4; i++) {
                    int mb = warp_m0 + i * 16 + g;
                    af[i][0] = Au[(ks + r) * APAD_T + mb];
                    af[i][1] = Au[(ks + r) * APAD_T + mb + 8];
                    af[i][2] = Au[(ks + r + 4) * APAD_T + mb];
                    af[i][3] = Au[(ks + r + 4) * APAD_T + mb + 8];
                }
            } else {
                int m_off = ((lane >> 3) & 1) * 8 + (lane & 7);
                int k_off = ks + (lane >> 4) * 4;
                #pragma unroll
                for (int i = 0; i < 4; i++) {
                    uint32_t addr = a_ldsm_base +
                        ((warp_m0 + i * 16 + m_off) * APAD_N + k_off) * 4;
                    ldsm_x4(af[i][0], af[i][1], af[i][2], af[i][3], addr);
                }
            }
            if (TB) {
                #pragma unroll
                for (int j = 0; j < 8; j++) {
                    int nb = warp_n0 + j * 8 + g;
                    bf[j][0] = Bu[nb * BPAD_T + ks + r];
                    bf[j][1] = Bu[nb * BPAD_T + ks + r + 4];
                }
            } else {
                #pragma unroll
                for (int j = 0; j < 8; j++) {
                    int nb = warp_n0 + j * 8 + g;
                    bf[j][0] = Bu[(ks + r) * BPAD_N + nb];
                    bf[j][1] = Bu[(ks + r + 4) * BPAD_N + nb];
                }
            }
            #pragma unroll
            for (int i = 0; i < 4; i++)
                #pragma unroll
                for (int j = 0; j < 8; j++)
                    mma_tf32(acc[i][j], af[i], bf[j]);
        }
        __syncthreads();
    }

    cp_wait_all();

    // ---- epilogue
    #pragma unroll
    for (int i = 0; i < 4; i++) {
        int m = m0 + warp_m0 + i * 16 + g;
        float bv0 = bias ? bias[m] : 0.f;
        float bv8 = bias ? bias[m + 8] : 0.f;
        #pragma unroll
        for (int j = 0; j < 8; j++) {
            int n = n0 + warp_n0 + j * 8 + 2 * r;
            float2 lo, hi;
            lo.x = acc[i][j][0] * alpha + bv0;
            lo.y = acc[i][j][1] * alpha + bv0;
            hi.x = acc[i][j][2] * alpha + bv8;
            hi.y = acc[i][j][3] * alpha + bv8;
            if (doRelu) {
                lo.x = fmaxf(lo.x, 0.f); lo.y = fmaxf(lo.y, 0.f);
                hi.x = fmaxf(hi.x, 0.f); hi.y = fmaxf(hi.y, 0.f);
            }
            *(float2*)&Cb[(size_t)m * ldc + n] = lo;
            *(float2*)&Cb[(size_t)(m + 8) * ldc + n] = hi;
        }
    }
}

// Sum split-K partials
__global__ void reduce_split(const float* __restrict__ in,
                             float* __restrict__ out, int per, int nsplit,
                             size_t total) {
    size_t i = (size_t)blockIdx.x * blockDim.x + threadIdx.x;
    if (i >= total) return;
    size_t b = i / per;
    size_t r = i - b * per;
    const float* src = in + b * (size_t)nsplit * per + r;
    float s = 0.f;
    for (int ss = 0; ss < nsplit; ss++) s += src[(size_t)ss * per];
    out[i] = s;
}

// ---------------------------------------------------------------------------
// smem sizes per instantiation (bytes, 2 stages)
static constexpr int SM_FF = 2 * (128 * 36 + 32 * 264) * 4;   // 104448
static constexpr int SM_FT = 2 * (128 * 36 + 256 * 36) * 4;   // 110592
static constexpr int SM_TF = 2 * (32 * 136 + 32 * 264) * 4;   // 102400

extern "C" void kernel_launch(void* const* d_in, const int* in_sizes, int n_in,
                              void* d_out, int out_size) {
    (void)in_sizes; (void)n_in; (void)out_size;
    const float* feat = (const float*)d_in[0];
    const float* wp1 = (const float*)d_in[2];
    const float* bp1 = (const float*)d_in[3];
    const float* wp2 = (const float*)d_in[4];
    const float* bp2 = (const float*)d_in[5];
    const float* wo1 = (const float*)d_in[6];
    const float* bo1 = (const float*)d_in[7];
    const float* wo2 = (const float*)d_in[8];
    const float* bo2 = (const float*)d_in[9];
    const float* wd  = (const float*)d_in[10];
    const float* bd  = (const float*)d_in[11];
    const float* wu  = (const float*)d_in[12];
    const float* bu  = (const float*)d_in[13];
    const float* wout = (const float*)d_in[14];
    const float* bout = (const float*)d_in[15];
    float* outp = (float*)d_out;

    float *bufA, *bufB, *bufC, *bufD, *ctxp, *smallp;
    cudaGetSymbolAddress((void**)&bufA, g_bufA);
    cudaGetSymbolAddress((void**)&bufB, g_bufB);
    cudaGetSymbolAddress((void**)&bufC, g_bufC);
    cudaGetSymbolAddress((void**)&bufD, g_bufD);
    cudaGetSymbolAddress((void**)&ctxp, g_context);
    cudaGetSymbolAddress((void**)&smallp, g_small);
    float* c1p = smallp;                 // [B,256,512]
    float* kmp = smallp + 524288;        // [B,256,512]
    float* vp  = smallp + 1048576;       // [B,256,512]

    const size_t sBN = (size_t)CDIM * NDIM;
    const size_t sKN = (size_t)KEYD * NDIM;
    const size_t sCC = (size_t)CDIM * CDIM;
    const size_t sKC = (size_t)KEYD * CDIM;

    cudaFuncSetAttribute(softmax_rows16k,
                         cudaFuncAttributeMaxDynamicSharedMemorySize, 65536);
    cudaFuncSetAttribute(gemm_tf32<false, false, false>,
                         cudaFuncAttributeMaxDynamicSharedMemorySize, SM_FF);
    cudaFuncSetAttribute(gemm_tf32<false, false, true>,
                         cudaFuncAttributeMaxDynamicSharedMemorySize, SM_FF);
    cudaFuncSetAttribute(gemm_tf32<false, true, false>,
                         cudaFuncAttributeMaxDynamicSharedMemorySize, SM_FT);
    cudaFuncSetAttribute(gemm_tf32<true, false, false>,
                         cudaFuncAttributeMaxDynamicSharedMemorySize, SM_TF);

    // 1) pw = softmax(x, axis=-1)  -> bufA
    softmax_rows16k<<<BATCH * CDIM, 256, 65536>>>(feat, bufA);

    // 2) context partials = X * PW^T (split-K=16)  -> bufD
    {
        dim3 g(CDIM / 256, CDIM / 128, BATCH * 16);
        gemm_tf32<false, true, false><<<g, 256, SM_FT>>>(
            feat, sBN, NDIM, bufA, sBN, NDIM, nullptr, 0, 0,
            bufD, sCC, CDIM, nullptr, 1.f, 0, CDIM, CDIM, NDIM, 16);
    }
    // 3) reduce split-K -> g_context
    {
        size_t total = (size_t)BATCH * sCC;
        reduce_split<<<(unsigned)((total + 255) / 256), 256>>>(
            bufD, ctxp, (int)sCC, 16, total);
    }
    // 4) t1 = relu(wp1 @ x + bp1)  -> bufB
    {
        dim3 g(NDIM / 256, KEYD / 128, BATCH);
        gemm_tf32<false, false, false><<<g, 256, SM_FF>>>(
            wp1, 0, CDIM, feat, sBN, NDIM, nullptr, 0, 0,
            bufB, sKN, NDIM, bp1, 1.f, 1, KEYD, NDIM, CDIM, 1);
    }
    // 5) q = relu(wp2 @ t1 + bp2)  -> bufC
    {
        dim3 g(NDIM / 256, KEYD / 128, BATCH);
        gemm_tf32<false, false, false><<<g, 256, SM_FF>>>(
            wp2, 0, KEYD, bufB, sKN, NDIM, nullptr, 0, 0,
            bufC, sKN, NDIM, bp2, 1.f, 1, KEYD, NDIM, KEYD, 1);
    }
    // 6) c1 = relu(wo1 @ context + bo1)  -> c1p
    {
        dim3 g(CDIM / 256, KEYD / 128, BATCH);
        gemm_tf32<false, false, false><<<g, 256, SM_FF>>>(
            wo1, 0, CDIM, ctxp, sCC, CDIM, nullptr, 0, 0,
            c1p, sKC, CDIM, bo1, 1.f, 1, KEYD, CDIM, CDIM, 1);
    }
    // 7) kmat = relu(wo2 @ c1 + bo2)  -> kmp
    {
        dim3 g(CDIM / 256, KEYD / 128, BATCH);
        gemm_tf32<false, false, false><<<g, 256, SM_FF>>>(
            wo2, 0, KEYD, c1p, sKC, CDIM, nullptr, 0, 0,
            kmp, sKC, CDIM, bo2, 1.f, 1, KEYD, CDIM, KEYD, 1);
    }
    // 8) v = relu(wd @ context + bd)  -> vp
    {
        dim3 g(CDIM / 256, KEYD / 128, BATCH);
        gemm_tf32<false, false, false><<<g, 256, SM_FF>>>(
            wd, 0, CDIM, ctxp, sCC, CDIM, nullptr, 0, 0,
            vp, sKC, CDIM, bd, 1.f, 1, KEYD, CDIM, CDIM, 1);
    }
    // 9) sim = (Q^T K) * KEY^-0.5   -> bufA  [B, N, 512]
    {
        dim3 g(CDIM / 256, NDIM / 128, BATCH);
        gemm_tf32<true, false, false><<<g, 256, SM_TF>>>(
            bufC, sKN, NDIM, kmp, sKC, CDIM, nullptr, 0, 0,
            bufA, (size_t)NDIM * CDIM, CDIM, nullptr, 0.0625f, 0,
            NDIM, CDIM, KEYD, 1);
    }
    // 10) softmax over K=512 (in place)
    softmax_k512<<<BATCH * NDIM, 128>>>(bufA);

    // 11) attn ctx = V @ SIM^T  -> bufB  [B,256,N]
    {
        dim3 g(NDIM / 256, KEYD / 128, BATCH);
        gemm_tf32<false, true, false><<<g, 256, SM_FT>>>(
            vp, sKC, CDIM, bufA, (size_t)NDIM * CDIM, CDIM, nullptr, 0, 0,
            bufB, sKN, NDIM, nullptr, 1.f, 0, KEYD, NDIM, CDIM, 1);
    }
    // 12) ctx_up = relu(wu @ attn_ctx + bu)  -> bufD  [B,512,N]
    {
        dim3 g(NDIM / 256, CDIM / 128, BATCH);
        gemm_tf32<false, false, false><<<g, 256, SM_FF>>>(
            wu, 0, KEYD, bufB, sKN, NDIM, nullptr, 0, 0,
            bufD, sBN, NDIM, bu, 1.f, 1, CDIM, NDIM, KEYD, 1);
    }
    // 13) out = relu(wout @ concat(ctx_up, x) + bout)  -> d_out
    {
        dim3 g(NDIM / 256, CDIM / 128, BATCH);
        gemm_tf32<false, false, true><<<g, 256, SM_FF>>>(
            wout, 0, 2 * CDIM, bufD, sBN, NDIM, feat, sBN, CDIM,
            outp, sBN, NDIM, bout, 1.f, 1, CDIM, NDIM, 2 * CDIM, 1);
    }
}

// round 6
// speedup vs baseline: 4.0857x; 1.2417x over previous
#include <cuda_runtime.h>
#include <cuda_bf16.h>
#include <cstdint>
#include <cstddef>

// ---------------------------------------------------------------------------
// OCR head on GB300 — Round 6: mma.sync TF32 (sm_103 family target: tcgen05
// unavailable in this build flow). Round-4 design with CTA halved to
// 128 threads / 4 warps (CTA tile 128x128x32, warp tile 64x64) so TWO CTAs
// fit per SM (regs+smem both allow it) — cross-CTA overlap hides the
// cp.async-wait / barrier bubbles that bounded Round 4.
// ---------------------------------------------------------------------------

#define BATCH 4
#define CDIM 512
#define NDIM 16384
#define KEYD 256

__device__ float g_bufA[33554432]; // pw [B,512,N], later sim [B,N,512]
__device__ float g_bufB[16777216]; // t1 [B,256,N], later attn ctx [B,256,N]
__device__ float g_bufC[16777216]; // q  [B,256,N]
__device__ float g_bufD[33554432]; // split-K partials, later ctx_up [B,512,N]
__device__ float g_context[1048576];  // [B,512,512]
__device__ float g_small[1572864];    // c1 / kmat / v : each [B,256,512]

// ---------------------------------------------------------------------------
__global__ void softmax_rows16k(const float* __restrict__ x,
                                float* __restrict__ out) {
    extern __shared__ float srow[];        // 16384 floats
    __shared__ float red[256];
    const int NC = NDIM;
    size_t row = blockIdx.x;
    const float* xr = x + row * (size_t)NC;
    float* outr = out + row * (size_t)NC;
    int tid = threadIdx.x;

    float m = -3.4e38f;
    for (int i = tid * 4; i < NC; i += 1024) {
        float4 v = *(const float4*)&xr[i];
        *(float4*)&srow[i] = v;
        m = fmaxf(m, fmaxf(fmaxf(v.x, v.y), fmaxf(v.z, v.w)));
    }
    red[tid] = m;
    __syncthreads();
    for (int s = 128; s > 0; s >>= 1) {
        if (tid < s) red[tid] = fmaxf(red[tid], red[tid + s]);
        __syncthreads();
    }
    m = red[0];
    __syncthreads();

    float sum = 0.f;
    for (int i = tid * 4; i < NC; i += 1024) {
        float4 v = *(float4*)&srow[i];
        v.x = __expf(v.x - m); v.y = __expf(v.y - m);
        v.z = __expf(v.z - m); v.w = __expf(v.w - m);
        *(float4*)&srow[i] = v;
        sum += v.x + v.y + v.z + v.w;
    }
    red[tid] = sum;
    __syncthreads();
    for (int s = 128; s > 0; s >>= 1) {
        if (tid < s) red[tid] += red[tid + s];
        __syncthreads();
    }
    float inv = 1.f / red[0];

    for (int i = tid * 4; i < NC; i += 1024) {
        float4 v = *(float4*)&srow[i];
        v.x *= inv; v.y *= inv; v.z *= inv; v.w *= inv;
        *(float4*)&outr[i] = v;
    }
}

// ---------------------------------------------------------------------------
__global__ void softmax_k512(float* __restrict__ sim) {
    __shared__ float redm[4];
    __shared__ float reds[4];
    size_t row = blockIdx.x;
    float* r = sim + row * 512;
    int tid = threadIdx.x;

    float4 v = *(float4*)&r[tid * 4];
    float m = fmaxf(fmaxf(v.x, v.y), fmaxf(v.z, v.w));
    #pragma unroll
    for (int o = 16; o > 0; o >>= 1)
        m = fmaxf(m, __shfl_xor_sync(0xffffffffu, m, o));
    if ((tid & 31) == 0) redm[tid >> 5] = m;
    __syncthreads();
    m = fmaxf(fmaxf(redm[0], redm[1]), fmaxf(redm[2], redm[3]));

    float e0 = __expf(v.x - m), e1 = __expf(v.y - m);
    float e2 = __expf(v.z - m), e3 = __expf(v.w - m);
    float s = e0 + e1 + e2 + e3;
    #pragma unroll
    for (int o = 16; o > 0; o >>= 1)
        s += __shfl_xor_sync(0xffffffffu, s, o);
    if ((tid & 31) == 0) reds[tid >> 5] = s;
    __syncthreads();
    float inv = 1.f / (reds[0] + reds[1] + reds[2] + reds[3]);

    float4 o4 = make_float4(e0 * inv, e1 * inv, e2 * inv, e3 * inv);
    *(float4*)&r[tid * 4] = o4;
}

// ---------------------------------------------------------------------------
__device__ __forceinline__ void mma_tf32(float c[4], const uint32_t a[4],
                                         const uint32_t b[2]) {
    asm volatile(
        "mma.sync.aligned.m16n8k8.row.col.f32.tf32.tf32.f32 "
        "{%0,%1,%2,%3}, {%4,%5,%6,%7}, {%8,%9}, {%0,%1,%2,%3};"
        : "+f"(c[0]), "+f"(c[1]), "+f"(c[2]), "+f"(c[3])
        : "r"(a[0]), "r"(a[1]), "r"(a[2]), "r"(a[3]), "r"(b[0]), "r"(b[1]));
}

__device__ __forceinline__ void cp16(uint32_t dst, const float* src) {
    asm volatile("cp.async.cg.shared.global [%0], [%1], 16;\n"
                 :: "r"(dst), "l"(src));
}
__device__ __forceinline__ void cp_commit() {
    asm volatile("cp.async.commit_group;\n" ::: "memory");
}
__device__ __forceinline__ void cp_wait0() {
    asm volatile("cp.async.wait_group 0;\n" ::: "memory");
}
__device__ __forceinline__ void cp_wait_all() {
    asm volatile("cp.async.wait_all;\n" ::: "memory");
}
__device__ __forceinline__ void ldsm_x4(uint32_t& r0, uint32_t& r1,
                                        uint32_t& r2, uint32_t& r3,
                                        uint32_t addr) {
    asm volatile("ldmatrix.sync.aligned.m8n8.x4.shared.b16 {%0,%1,%2,%3}, [%4];"
                 : "=r"(r0), "=r"(r1), "=r"(r2), "=r"(r3) : "r"(addr));
}

// ---------------------------------------------------------------------------
// TF32 batched GEMM: C[m,n] = act(alpha * sum_k opA(m,k)*opB(k,n) + bias[m])
//   TA: A stored [K,M] (lda) else [M,K] ; TB: B stored [N,K] else [K,N].
//   CONCAT (TB=false): k rows >= ksplitB come from B2.
//   gridDim.z = batch*nsplit (split-K partials at C + z*sCz).
// CTA tile 128x128x32, 128 threads, 4 warps (2m x 2n), warp tile 64x64.
// Two CTAs co-resident per SM. Requires M%128==0, N%128==0, K%32==0.
// ---------------------------------------------------------------------------
template <bool TA, bool TB, bool CONCAT>
__global__ void __launch_bounds__(128, 2)
gemm_tf32(const float* __restrict__ A, size_t sA, int lda,
          const float* __restrict__ B, size_t sB, int ldb,
          const float* __restrict__ B2, size_t sB2, int ksplitB,
          float* __restrict__ C, size_t sCz, int ldc,
          const float* __restrict__ bias, float alpha, int doRelu,
          int M, int N, int K, int nsplit) {
    constexpr int BM = 128, BN = 128, BK = 32;
    constexpr int APAD_T = 136;   // TA=true : As[k][m], pad 128+8
    constexpr int APAD_N = 36;    // TA=false: As[m][k], pad 32+4
    constexpr int BPAD_T = 36;    // TB=true : Bs[n][k], pad 32+4
    constexpr int BPAD_N = 136;   // TB=false: Bs[k][n], pad 128+8
    constexpr int ASZ = TA ? BK * APAD_T : BM * APAD_N;
    constexpr int BSZ = TB ? BN * BPAD_T : BK * BPAD_N;

    extern __shared__ float smem[];
    float* Asm[2] = { smem, smem + ASZ + BSZ };
    float* Bsm[2] = { smem + ASZ, smem + 2 * ASZ + BSZ };

    int z = blockIdx.z;
    int b = z / nsplit;
    int sidx = z - b * nsplit;
    int kchunk = K / nsplit;
    int kbeg = sidx * kchunk;
    int niter = kchunk / BK;

    const float* Ab = A + (size_t)b * sA;
    const float* Bb = B + (size_t)b * sB;
    const float* B2b = CONCAT ? (B2 + (size_t)b * sB2) : (const float*)nullptr;
    float* Cb = C + (size_t)z * sCz;

    int m0 = blockIdx.y * BM;
    int n0 = blockIdx.x * BN;
    int tid = threadIdx.x;
    int warp = tid >> 5, lane = tid & 31;
    int g = lane >> 2, r = lane & 3;
    int wm = warp & 1, wn = warp >> 1;
    int warp_m0 = wm * 64, warp_n0 = wn * 64;

    float acc[4][8][4];
    #pragma unroll
    for (int i = 0; i < 4; i++)
        #pragma unroll
        for (int j = 0; j < 8; j++)
            #pragma unroll
            for (int e = 0; e < 4; e++) acc[i][j][e] = 0.f;

    // ---- async prefetch of one k-slab into stage st (128 threads)
    auto prefetch = [&](int st, int k0) {
        uint32_t abase = (uint32_t)__cvta_generic_to_shared(Asm[st]);
        uint32_t bbase = (uint32_t)__cvta_generic_to_shared(Bsm[st]);
        if (TA) {
            // [K,M] -> Asm[k][m] : 32 rows x 32 float4 chunks
            #pragma unroll
            for (int p = 0; p < 8; p++) {
                int c = tid + p * 128;
                int row = c >> 5, mc = (c & 31) * 4;
                cp16(abase + (row * APAD_T + mc) * 4,
                     &Ab[(size_t)(k0 + row) * lda + m0 + mc]);
            }
        } else {
            // [M,K] -> Asm[m][k] : 128 rows x 8 chunks
            #pragma unroll
            for (int p = 0; p < 8; p++) {
                int c = tid + p * 128;
                int row = c >> 3, kc = (c & 7) * 4;
                cp16(abase + (row * APAD_N + kc) * 4,
                     &Ab[(size_t)(m0 + row) * lda + k0 + kc]);
            }
        }
        if (TB) {
            // [N,K] -> Bsm[n][k] : 128 rows x 8 chunks
            #pragma unroll
            for (int p = 0; p < 8; p++) {
                int c = tid + p * 128;
                int row = c >> 3, kc = (c & 7) * 4;
                cp16(bbase + (row * BPAD_T + kc) * 4,
                     &Bb[(size_t)(n0 + row) * ldb + k0 + kc]);
            }
        } else {
            // [K,N] -> Bsm[k][n] : 32 rows x 32 chunks
            #pragma unroll
            for (int p = 0; p < 8; p++) {
                int c = tid + p * 128;
                int row = c >> 5, nc = (c & 31) * 4;
                int kr = k0 + row;
                const float* src;
                if (CONCAT && kr >= ksplitB)
                    src = &B2b[(size_t)(kr - ksplitB) * ldb + n0 + nc];
                else
                    src = &Bb[(size_t)kr * ldb + n0 + nc];
                cp16(bbase + (row * BPAD_N + nc) * 4, src);
            }
        }
        cp_commit();
    };

    prefetch(0, kbeg);

    for (int it = 0; it < niter; it++) {
        int st = it & 1;
        cp_wait0();
        __syncthreads();
        if (it + 1 < niter) prefetch(st ^ 1, kbeg + (it + 1) * BK);

        const uint32_t* Au = (const uint32_t*)Asm[st];
        const uint32_t* Bu = (const uint32_t*)Bsm[st];
        uint32_t a_ldsm_base = (uint32_t)__cvta_generic_to_shared(Asm[st]);

        #pragma unroll
        for (int ks = 0; ks < BK; ks += 8) {
            uint32_t af[4][4], bf[8][2];
            if (TA) {
                #pragma unroll
                for (int i = 0; i < 4; i++) {
                    int mb = warp_m0 + i * 16 + g;
                    af[i][0] = Au[(ks + r) * APAD_T + mb];
                    af[i][1] = Au[(ks + r) * APAD_T + mb + 8];
                    af[i][2] = Au[(ks + r + 4) * APAD_T + mb];
                    af[i][3] = Au[(ks + r + 4) * APAD_T + mb + 8];
                }
            } else {
                int m_off = ((lane >> 3) & 1) * 8 + (lane & 7);
                int k_off = ks + (lane >> 4) * 4;
                #pragma unroll
                for (int i = 0; i < 4; i++) {
                    uint32_t addr = a_ldsm_base +
                        ((warp_m0 + i * 16 + m_off) * APAD_N + k_off) * 4;
                    ldsm_x4(af[i][0], af[i][1], af[i][2], af[i][3], addr);
                }
            }
            if (TB) {
                #pragma unroll
                for (int j = 0; j < 8; j++) {
                    int nb = warp_n0 + j * 8 + g;
                    bf[j][0] = Bu[nb * BPAD_T + ks + r];
                    bf[j][1] = Bu[nb * BPAD_T + ks + r + 4];
                }
            } else {
                #pragma unroll
                for (int j = 0; j < 8; j++) {
                    int nb = warp_n0 + j * 8 + g;
                    bf[j][0] = Bu[(ks + r) * BPAD_N + nb];
                    bf[j][1] = Bu[(ks + r + 4) * BPAD_N + nb];
                }
            }
            #pragma unroll
            for (int i = 0; i < 4; i++)
                #pragma unroll
                for (int j = 0; j < 8; j++)
                    mma_tf32(acc[i][j], af[i], bf[j]);
        }
        __syncthreads();
    }

    cp_wait_all();

    // ---- epilogue
    #pragma unroll
    for (int i = 0; i < 4; i++) {
        int m = m0 + warp_m0 + i * 16 + g;
        float bv0 = bias ? bias[m] : 0.f;
        float bv8 = bias ? bias[m + 8] : 0.f;
        #pragma unroll
        for (int j = 0; j < 8; j++) {
            int n = n0 + warp_n0 + j * 8 + 2 * r;
            float2 lo, hi;
            lo.x = acc[i][j][0] * alpha + bv0;
            lo.y = acc[i][j][1] * alpha + bv0;
            hi.x = acc[i][j][2] * alpha + bv8;
            hi.y = acc[i][j][3] * alpha + bv8;
            if (doRelu) {
                lo.x = fmaxf(lo.x, 0.f); lo.y = fmaxf(lo.y, 0.f);
                hi.x = fmaxf(hi.x, 0.f); hi.y = fmaxf(hi.y, 0.f);
            }
            *(float2*)&Cb[(size_t)m * ldc + n] = lo;
            *(float2*)&Cb[(size_t)(m + 8) * ldc + n] = hi;
        }
    }
}

// Sum split-K partials
__global__ void reduce_split(const float* __restrict__ in,
                             float* __restrict__ out, int per, int nsplit,
                             size_t total) {
    size_t i = (size_t)blockIdx.x * blockDim.x + threadIdx.x;
    if (i >= total) return;
    size_t b = i / per;
    size_t r = i - b * per;
    const float* src = in + b * (size_t)nsplit * per + r;
    float s = 0.f;
    for (int ss = 0; ss < nsplit; ss++) s += src[(size_t)ss * per];
    out[i] = s;
}

// ---------------------------------------------------------------------------
// smem sizes per instantiation (bytes, 2 stages)
static constexpr int SM_FF = 2 * (128 * 36 + 32 * 136) * 4;   // 71680
static constexpr int SM_FT = 2 * (128 * 36 + 128 * 36) * 4;   // 73728
static constexpr int SM_TF = 2 * (32 * 136 + 32 * 136) * 4;   // 69632

extern "C" void kernel_launch(void* const* d_in, const int* in_sizes, int n_in,
                              void* d_out, int out_size) {
    (void)in_sizes; (void)n_in; (void)out_size;
    const float* feat = (const float*)d_in[0];
    const float* wp1 = (const float*)d_in[2];
    const float* bp1 = (const float*)d_in[3];
    const float* wp2 = (const float*)d_in[4];
    const float* bp2 = (const float*)d_in[5];
    const float* wo1 = (const float*)d_in[6];
    const float* bo1 = (const float*)d_in[7];
    const float* wo2 = (const float*)d_in[8];
    const float* bo2 = (const float*)d_in[9];
    const float* wd  = (const float*)d_in[10];
    const float* bd  = (const float*)d_in[11];
    const float* wu  = (const float*)d_in[12];
    const float* bu  = (const float*)d_in[13];
    const float* wout = (const float*)d_in[14];
    const float* bout = (const float*)d_in[15];
    float* outp = (float*)d_out;

    float *bufA, *bufB, *bufC, *bufD, *ctxp, *smallp;
    cudaGetSymbolAddress((void**)&bufA, g_bufA);
    cudaGetSymbolAddress((void**)&bufB, g_bufB);
    cudaGetSymbolAddress((void**)&bufC, g_bufC);
    cudaGetSymbolAddress((void**)&bufD, g_bufD);
    cudaGetSymbolAddress((void**)&ctxp, g_context);
    cudaGetSymbolAddress((void**)&smallp, g_small);
    float* c1p = smallp;                 // [B,256,512]
    float* kmp = smallp + 524288;        // [B,256,512]
    float* vp  = smallp + 1048576;       // [B,256,512]

    const size_t sBN = (size_t)CDIM * NDIM;
    const size_t sKN = (size_t)KEYD * NDIM;
    const size_t sCC = (size_t)CDIM * CDIM;
    const size_t sKC = (size_t)KEYD * CDIM;

    cudaFuncSetAttribute(softmax_rows16k,
                         cudaFuncAttributeMaxDynamicSharedMemorySize, 65536);
    cudaFuncSetAttribute(gemm_tf32<false, false, false>,
                         cudaFuncAttributeMaxDynamicSharedMemorySize, SM_FF);
    cudaFuncSetAttribute(gemm_tf32<false, false, true>,
                         cudaFuncAttributeMaxDynamicSharedMemorySize, SM_FF);
    cudaFuncSetAttribute(gemm_tf32<false, true, false>,
                         cudaFuncAttributeMaxDynamicSharedMemorySize, SM_FT);
    cudaFuncSetAttribute(gemm_tf32<true, false, false>,
                         cudaFuncAttributeMaxDynamicSharedMemorySize, SM_TF);

    // 1) pw = softmax(x, axis=-1)  -> bufA
    softmax_rows16k<<<BATCH * CDIM, 256, 65536>>>(feat, bufA);

    // 2) context partials = X * PW^T (split-K=16)  -> bufD
    {
        dim3 g(CDIM / 128, CDIM / 128, BATCH * 16);
        gemm_tf32<false, true, false><<<g, 128, SM_FT>>>(
            feat, sBN, NDIM, bufA, sBN, NDIM, nullptr, 0, 0,
            bufD, sCC, CDIM, nullptr, 1.f, 0, CDIM, CDIM, NDIM, 16);
    }
    // 3) reduce split-K -> g_context
    {
        size_t total = (size_t)BATCH * sCC;
        reduce_split<<<(unsigned)((total + 255) / 256), 256>>>(
            bufD, ctxp, (int)sCC, 16, total);
    }
    // 4) t1 = relu(wp1 @ x + bp1)  -> bufB
    {
        dim3 g(NDIM / 128, KEYD / 128, BATCH);
        gemm_tf32<false, false, false><<<g, 128, SM_FF>>>(
            wp1, 0, CDIM, feat, sBN, NDIM, nullptr, 0, 0,
            bufB, sKN, NDIM, bp1, 1.f, 1, KEYD, NDIM, CDIM, 1);
    }
    // 5) q = relu(wp2 @ t1 + bp2)  -> bufC
    {
        dim3 g(NDIM / 128, KEYD / 128, BATCH);
        gemm_tf32<false, false, false><<<g, 128, SM_FF>>>(
            wp2, 0, KEYD, bufB, sKN, NDIM, nullptr, 0, 0,
            bufC, sKN, NDIM, bp2, 1.f, 1, KEYD, NDIM, KEYD, 1);
    }
    // 6) c1 = relu(wo1 @ context + bo1)  -> c1p
    {
        dim3 g(CDIM / 128, KEYD / 128, BATCH);
        gemm_tf32<false, false, false><<<g, 128, SM_FF>>>(
            wo1, 0, CDIM, ctxp, sCC, CDIM, nullptr, 0, 0,
            c1p, sKC, CDIM, bo1, 1.f, 1, KEYD, CDIM, CDIM, 1);
    }
    // 7) kmat = relu(wo2 @ c1 + bo2)  -> kmp
    {
        dim3 g(CDIM / 128, KEYD / 128, BATCH);
        gemm_tf32<false, false, false><<<g, 128, SM_FF>>>(
            wo2, 0, KEYD, c1p, sKC, CDIM, nullptr, 0, 0,
            kmp, sKC, CDIM, bo2, 1.f, 1, KEYD, CDIM, KEYD, 1);
    }
    // 8) v = relu(wd @ context + bd)  -> vp
    {
        dim3 g(CDIM / 128, KEYD / 128, BATCH);
        gemm_tf32<false, false, false><<<g, 128, SM_FF>>>(
            wd, 0, CDIM, ctxp, sCC, CDIM, nullptr, 0, 0,
            vp, sKC, CDIM, bd, 1.f, 1, KEYD, CDIM, CDIM, 1);
    }
    // 9) sim = (Q^T K) * KEY^-0.5   -> bufA  [B, N, 512]
    {
        dim3 g(CDIM / 128, NDIM / 128, BATCH);
        gemm_tf32<true, false, false><<<g, 128, SM_TF>>>(
            bufC, sKN, NDIM, kmp, sKC, CDIM, nullptr, 0, 0,
            bufA, (size_t)NDIM * CDIM, CDIM, nullptr, 0.0625f, 0,
            NDIM, CDIM, KEYD, 1);
    }
    // 10) softmax over K=512 (in place)
    softmax_k512<<<BATCH * NDIM, 128>>>(bufA);

    // 11) attn ctx = V @ SIM^T  -> bufB  [B,256,N]
    {
        dim3 g(NDIM / 128, KEYD / 128, BATCH);
        gemm_tf32<false, true, false><<<g, 128, SM_FT>>>(
            vp, sKC, CDIM, bufA, (size_t)NDIM * CDIM, CDIM, nullptr, 0, 0,
            bufB, sKN, NDIM, nullptr, 1.f, 0, KEYD, NDIM, CDIM, 1);
    }
    // 12) ctx_up = relu(wu @ attn_ctx + bu)  -> bufD  [B,512,N]
    {
        dim3 g(NDIM / 128, CDIM / 128, BATCH);
        gemm_tf32<false, false, false><<<g, 128, SM_FF>>>(
            wu, 0, KEYD, bufB, sKN, NDIM, nullptr, 0, 0,
            bufD, sBN, NDIM, bu, 1.f, 1, CDIM, NDIM, KEYD, 1);
    }
    // 13) out = relu(wout @ concat(ctx_up, x) + bout)  -> d_out
    {
        dim3 g(NDIM / 128, CDIM / 128, BATCH);
        gemm_tf32<false, false, true><<<g, 128, SM_FF>>>(
            wout, 0, 2 * CDIM, bufD, sBN, NDIM, feat, sBN, CDIM,
            outp, sBN, NDIM, bout, 1.f, 1, CDIM, NDIM, 2 * CDIM, 1);
    }
}

// round 7
// speedup vs baseline: 6.3272x; 1.5486x over previous
#include <cuda_runtime.h>
#include <cuda_fp16.h>
#include <cstdint>
#include <cstddef>

// ---------------------------------------------------------------------------
// OCR head on GB300 — Round 7: fp16 tensor cores (mma.sync.m16n8k16.f16,
// fp32 accumulate). fp16 mantissa == tf32 mantissa, values all O(1), so
// precision matches the tf32 path while HMMA rate and operand bandwidth
// double. All operands stored fp16 (rn); split-K partials fp32.
// CTA 128x128x64(halves), 128 thr / 4 warps, warp tile 64x64, 2 CTAs/SM,
// cp.async double buffering, all fragments via ldmatrix(.trans).
// ---------------------------------------------------------------------------

#define BATCH 4
#define CDIM 512
#define NDIM 16384
#define KEYD 256

// fp16 buffers
__device__ __half g_featH[33554432];  // feat   [B,512,N]
__device__ __half g_pwH[33554432];    // softmax(feat) [B,512,N]
__device__ __half g_simH[33554432];   // sim    [B,N,512] (row-major tokens)
__device__ __half g_uH[33554432];     // ctx_up [B,512,N]
__device__ __half g_t1H[16777216];    // t1 [B,256,N]; later attn ctx [B,256,N]
__device__ __half g_qH[16777216];     // q  [B,256,N]
__device__ __half g_ctxH[1048576];    // context [B,512,512]
__device__ __half g_c1H[524288];      // [B,256,512]
__device__ __half g_kmH[524288];      // [B,256,512]
__device__ __half g_vH[524288];       // [B,256,512]
__device__ __half g_wH[1179648];      // converted weights (packed)
// fp32 split-K partials
__device__ float g_split[16777216];   // [B*16,512,512]

// ---------------------------------------------------------------------------
__device__ __forceinline__ void mma_f16(float c[4], const uint32_t a[4],
                                        const uint32_t b[2]) {
    asm volatile(
        "mma.sync.aligned.m16n8k16.row.col.f32.f16.f16.f32 "
        "{%0,%1,%2,%3}, {%4,%5,%6,%7}, {%8,%9}, {%0,%1,%2,%3};"
        : "+f"(c[0]), "+f"(c[1]), "+f"(c[2]), "+f"(c[3])
        : "r"(a[0]), "r"(a[1]), "r"(a[2]), "r"(a[3]), "r"(b[0]), "r"(b[1]));
}
__device__ __forceinline__ void cp16(uint32_t dst, const void* src) {
    asm volatile("cp.async.cg.shared.global [%0], [%1], 16;\n"
                 :: "r"(dst), "l"(src));
}
__device__ __forceinline__ void cp_commit() {
    asm volatile("cp.async.commit_group;\n" ::: "memory");
}
__device__ __forceinline__ void cp_wait0() {
    asm volatile("cp.async.wait_group 0;\n" ::: "memory");
}
__device__ __forceinline__ void cp_wait_all() {
    asm volatile("cp.async.wait_all;\n" ::: "memory");
}
__device__ __forceinline__ void ldsm_x4(uint32_t& r0, uint32_t& r1,
                                        uint32_t& r2, uint32_t& r3,
                                        uint32_t addr) {
    asm volatile("ldmatrix.sync.aligned.m8n8.x4.shared.b16 {%0,%1,%2,%3}, [%4];"
                 : "=r"(r0), "=r"(r1), "=r"(r2), "=r"(r3) : "r"(addr));
}
__device__ __forceinline__ void ldsm_x4_t(uint32_t& r0, uint32_t& r1,
                                          uint32_t& r2, uint32_t& r3,
                                          uint32_t addr) {
    asm volatile("ldmatrix.sync.aligned.m8n8.x4.trans.shared.b16 {%0,%1,%2,%3}, [%4];"
                 : "=r"(r0), "=r"(r1), "=r"(r2), "=r"(r3) : "r"(addr));
}

// ---------------------------------------------------------------------------
// fp16 batched GEMM: C[m,n] = act(alpha * sum_k opA(m,k)*opB(k,n) + bias[m])
//   TA: A stored [K,M] (lda halves) else [M,K]; TB: B stored [N,K] else [K,N].
//   CONCAT (TB=false): k rows >= ksplitB come from B2 (same ldb).
//   outHalf: write __half C, else float C. gridDim.z = batch*nsplit.
// CTA tile 128x128, BK=64 halves, 128 threads, warp tile 64x64.
// Requires M%128==0, N%128==0, K%64==0.
// ---------------------------------------------------------------------------
template <bool TA, bool TB, bool CONCAT>
__global__ void __launch_bounds__(128, 2)
gemm_f16(const __half* __restrict__ A, size_t sA, int lda,
         const __half* __restrict__ B, size_t sB, int ldb,
         const __half* __restrict__ B2, int ksplitB,
         void* __restrict__ Cv, size_t sCz, int ldc,
         const float* __restrict__ bias, float alpha, int doRelu, int outHalf,
         int K, int nsplit) {
    constexpr int SA_ROW = 144;     // [m][k]: 64 halves +8 pad = 144 B
    constexpr int SKM_ROW = 272;    // [k][m]/[k][n]: 128 halves +8 pad = 272 B
    constexpr int ASZ = TA ? 64 * SKM_ROW : 128 * SA_ROW;
    constexpr int BSZ = TB ? 128 * SA_ROW : 64 * SKM_ROW;
    constexpr int STG = ASZ + BSZ;

    extern __shared__ __align__(16) char smem[];
    uint32_t base = (uint32_t)__cvta_generic_to_shared(smem);

    int z = blockIdx.z;
    int b = z / nsplit;
    int sidx = z - b * nsplit;
    int kchunk = K / nsplit;
    int kbeg = sidx * kchunk;
    int niter = kchunk >> 6;

    const __half* Ab = A + (size_t)b * sA;
    const __half* Bb = B + (size_t)b * sB;
    const __half* B2b = CONCAT ? (B2 + (size_t)b * sB) : (const __half*)nullptr;

    int m0 = blockIdx.y * 128;
    int n0 = blockIdx.x * 128;
    int tid = threadIdx.x;
    int warp = tid >> 5, lane = tid & 31;
    int g = lane >> 2, r = lane & 3;
    int wm = warp & 1, wn = warp >> 1;
    int warp_m0 = wm * 64, warp_n0 = wn * 64;

    // ldmatrix per-lane selectors
    int mo8 = (lane & 7) + ((lane >> 3) & 1) * 8;  // non-trans row
    int khalf = lane >> 4;                         // non-trans col half (16B)
    int kq = (lane & 7) + ((lane >> 4) & 1) * 8;   // trans k-row within 16
    int chalf = (lane >> 3) & 1;                   // trans col half (16B)

    float acc[4][8][4];
    #pragma unroll
    for (int i = 0; i < 4; i++)
        #pragma unroll
        for (int j = 0; j < 8; j++)
            #pragma unroll
            for (int e = 0; e < 4; e++) acc[i][j][e] = 0.f;

    auto prefetch = [&](int st, int k0) {
        uint32_t ab = base + st * STG;
        uint32_t bb = ab + ASZ;
        if (TA) {
            // [K,M] -> sm[k][m]: 64 rows x 16 chunks
            #pragma unroll
            for (int p = 0; p < 8; p++) {
                int idx = tid + p * 128;
                int row = idx >> 4, mc = idx & 15;
                cp16(ab + row * SKM_ROW + mc * 16,
                     Ab + (size_t)(k0 + row) * lda + m0 + mc * 8);
            }
        } else {
            // [M,K] -> sm[m][k]: 128 rows x 8 chunks
            #pragma unroll
            for (int p = 0; p < 8; p++) {
                int idx = tid + p * 128;
                int row = idx >> 3, kc = idx & 7;
                cp16(ab + row * SA_ROW + kc * 16,
                     Ab + (size_t)(m0 + row) * lda + k0 + kc * 8);
            }
        }
        if (TB) {
            // [N,K] -> sm[n][k]: 128 rows x 8 chunks
            #pragma unroll
            for (int p = 0; p < 8; p++) {
                int idx = tid + p * 128;
                int row = idx >> 3, kc = idx & 7;
                cp16(bb + row * SA_ROW + kc * 16,
                     Bb + (size_t)(n0 + row) * ldb + k0 + kc * 8);
            }
        } else {
            // [K,N] -> sm[k][n]: 64 rows x 16 chunks
            #pragma unroll
            for (int p = 0; p < 8; p++) {
                int idx = tid + p * 128;
                int row = idx >> 4, nc = idx & 15;
                int kr = k0 + row;
                const __half* src;
                if (CONCAT && kr >= ksplitB)
                    src = B2b + (size_t)(kr - ksplitB) * ldb + n0 + nc * 8;
                else
                    src = Bb + (size_t)kr * ldb + n0 + nc * 8;
                cp16(bb + row * SKM_ROW + nc * 16, src);
            }
        }
        cp_commit();
    };

    prefetch(0, kbeg);

    for (int it = 0; it < niter; it++) {
        int st = it & 1;
        cp_wait0();
        __syncthreads();
        if (it + 1 < niter) prefetch(st ^ 1, kbeg + (it + 1) * 64);

        uint32_t ab = base + st * STG;
        uint32_t bb = ab + ASZ;

        #pragma unroll
        for (int ks = 0; ks < 4; ks++) {   // 4 x k16 per 64-half stage
            uint32_t af[4][4], bf[8][2];
            if (TA) {
                #pragma unroll
                for (int i = 0; i < 4; i++) {
                    uint32_t addr = ab + (ks * 16 + kq) * SKM_ROW +
                                    (warp_m0 + i * 16) * 2 + chalf * 16;
                    ldsm_x4_t(af[i][0], af[i][1], af[i][2], af[i][3], addr);
                }
            } else {
                #pragma unroll
                for (int i = 0; i < 4; i++) {
                    uint32_t addr = ab + (warp_m0 + i * 16 + mo8) * SA_ROW +
                                    ks * 32 + khalf * 16;
                    ldsm_x4(af[i][0], af[i][1], af[i][2], af[i][3], addr);
                }
            }
            if (TB) {
                #pragma unroll
                for (int jj = 0; jj < 4; jj++) {
                    uint32_t addr = bb + (warp_n0 + jj * 16 + mo8) * SA_ROW +
                                    ks * 32 + khalf * 16;
                    ldsm_x4(bf[2 * jj][0], bf[2 * jj + 1][0],
                            bf[2 * jj][1], bf[2 * jj + 1][1], addr);
                }
            } else {
                #pragma unroll
                for (int jj = 0; jj < 4; jj++) {
                    uint32_t addr = bb + (ks * 16 + kq) * SKM_ROW +
                                    (warp_n0 + jj * 16) * 2 + chalf * 16;
                    ldsm_x4_t(bf[2 * jj][0], bf[2 * jj + 1][0],
                              bf[2 * jj][1], bf[2 * jj + 1][1], addr);
                }
            }
            #pragma unroll
            for (int i = 0; i < 4; i++)
                #pragma unroll
                for (int j = 0; j < 8; j++)
                    mma_f16(acc[i][j], af[i], bf[j]);
        }
        __syncthreads();
    }

    cp_wait_all();

    // ---- epilogue
    __half* Ch = (__half*)Cv + (size_t)z * sCz;
    float* Cf = (float*)Cv + (size_t)z * sCz;
    #pragma unroll
    for (int i = 0; i < 4; i++) {
        int m = m0 + warp_m0 + i * 16 + g;
        float bv0 = bias ? bias[m] : 0.f;
        float bv8 = bias ? bias[m + 8] : 0.f;
        #pragma unroll
        for (int j = 0; j < 8; j++) {
            int n = n0 + warp_n0 + j * 8 + 2 * r;
            float x0 = acc[i][j][0] * alpha + bv0;
            float x1 = acc[i][j][1] * alpha + bv0;
            float x2 = acc[i][j][2] * alpha + bv8;
            float x3 = acc[i][j][3] * alpha + bv8;
            if (doRelu) {
                x0 = fmaxf(x0, 0.f); x1 = fmaxf(x1, 0.f);
                x2 = fmaxf(x2, 0.f); x3 = fmaxf(x3, 0.f);
            }
            if (outHalf) {
                *(__half2*)&Ch[(size_t)m * ldc + n] = __floats2half2_rn(x0, x1);
                *(__half2*)&Ch[(size_t)(m + 8) * ldc + n] = __floats2half2_rn(x2, x3);
            } else {
                *(float2*)&Cf[(size_t)m * ldc + n] = make_float2(x0, x1);
                *(float2*)&Cf[(size_t)(m + 8) * ldc + n] = make_float2(x2, x3);
            }
        }
    }
}

// ---------------------------------------------------------------------------
// softmax over rows of 16384: emits fp16 softmax AND fp16 copy of input.
__global__ void softmax_rows16k(const float* __restrict__ x,
                                __half* __restrict__ pwout,
                                __half* __restrict__ xh) {
    extern __shared__ float srow[];
    __shared__ float red[256];
    const int NC = NDIM;
    size_t row = blockIdx.x;
    const float* xr = x + row * (size_t)NC;
    __half* pwr = pwout + row * (size_t)NC;
    __half* xhr = xh + row * (size_t)NC;
    int tid = threadIdx.x;

    float m = -3.4e38f;
    for (int i = tid * 4; i < NC; i += 1024) {
        float4 v = *(const float4*)&xr[i];
        *(float4*)&srow[i] = v;
        *(__half2*)&xhr[i] = __floats2half2_rn(v.x, v.y);
        *(__half2*)&xhr[i + 2] = __floats2half2_rn(v.z, v.w);
        m = fmaxf(m, fmaxf(fmaxf(v.x, v.y), fmaxf(v.z, v.w)));
    }
    red[tid] = m;
    __syncthreads();
    for (int s = 128; s > 0; s >>= 1) {
        if (tid < s) red[tid] = fmaxf(red[tid], red[tid + s]);
        __syncthreads();
    }
    m = red[0];
    __syncthreads();

    float sum = 0.f;
    for (int i = tid * 4; i < NC; i += 1024) {
        float4 v = *(float4*)&srow[i];
        v.x = __expf(v.x - m); v.y = __expf(v.y - m);
        v.z = __expf(v.z - m); v.w = __expf(v.w - m);
        *(float4*)&srow[i] = v;
        sum += v.x + v.y + v.z + v.w;
    }
    red[tid] = sum;
    __syncthreads();
    for (int s = 128; s > 0; s >>= 1) {
        if (tid < s) red[tid] += red[tid + s];
        __syncthreads();
    }
    float inv = 1.f / red[0];

    for (int i = tid * 4; i < NC; i += 1024) {
        float4 v = *(float4*)&srow[i];
        *(__half2*)&pwr[i] = __floats2half2_rn(v.x * inv, v.y * inv);
        *(__half2*)&pwr[i + 2] = __floats2half2_rn(v.z * inv, v.w * inv);
    }
}

// softmax over rows of 512 fp16 (in place). grid = B*N, 128 threads.
__global__ void softmax_k512h(__half* __restrict__ sim) {
    __shared__ float redm[4];
    __shared__ float reds[4];
    size_t row = blockIdx.x;
    __half2* rp = (__half2*)(sim + row * 512);
    int tid = threadIdx.x;

    __half2 h0 = rp[tid * 2], h1 = rp[tid * 2 + 1];
    float2 f0 = __half22float2(h0), f1 = __half22float2(h1);
    float m = fmaxf(fmaxf(f0.x, f0.y), fmaxf(f1.x, f1.y));
    #pragma unroll
    for (int o = 16; o > 0; o >>= 1)
        m = fmaxf(m, __shfl_xor_sync(0xffffffffu, m, o));
    if ((tid & 31) == 0) redm[tid >> 5] = m;
    __syncthreads();
    m = fmaxf(fmaxf(redm[0], redm[1]), fmaxf(redm[2], redm[3]));

    float e0 = __expf(f0.x - m), e1 = __expf(f0.y - m);
    float e2 = __expf(f1.x - m), e3 = __expf(f1.y - m);
    float s = e0 + e1 + e2 + e3;
    #pragma unroll
    for (int o = 16; o > 0; o >>= 1)
        s += __shfl_xor_sync(0xffffffffu, s, o);
    if ((tid & 31) == 0) reds[tid >> 5] = s;
    __syncthreads();
    float inv = 1.f / (reds[0] + reds[1] + reds[2] + reds[3]);

    rp[tid * 2] = __floats2half2_rn(e0 * inv, e1 * inv);
    rp[tid * 2 + 1] = __floats2half2_rn(e2 * inv, e3 * inv);
}

// Sum fp32 split-K partials -> fp16
__global__ void reduce_split(const float* __restrict__ in,
                             __half* __restrict__ out, int per, int nsplit,
                             size_t total) {
    size_t i = (size_t)blockIdx.x * blockDim.x + threadIdx.x;
    if (i >= total) return;
    size_t b = i / per;
    size_t r = i - b * per;
    const float* src = in + b * (size_t)nsplit * per + r;
    float s = 0.f;
    for (int ss = 0; ss < nsplit; ss++) s += src[(size_t)ss * per];
    out[i] = __float2half_rn(s);
}

// fp32 -> fp16 conversion
__global__ void f2h(const float* __restrict__ in, __half* __restrict__ out,
                    int n) {
    int i = (blockIdx.x * blockDim.x + threadIdx.x) * 4;
    if (i >= n) return;
    float4 v = *(const float4*)&in[i];
    *(__half2*)&out[i] = __floats2half2_rn(v.x, v.y);
    *(__half2*)&out[i + 2] = __floats2half2_rn(v.z, v.w);
}

// ---------------------------------------------------------------------------
// smem sizes (bytes, 2 stages)
static constexpr int SM_FF = 2 * (128 * 144 + 64 * 272);   // 71680
static constexpr int SM_FT = 2 * (128 * 144 + 128 * 144);  // 73728
static constexpr int SM_TF = 2 * (64 * 272 + 64 * 272);    // 69632

extern "C" void kernel_launch(void* const* d_in, const int* in_sizes, int n_in,
                              void* d_out, int out_size) {
    (void)in_sizes; (void)n_in; (void)out_size;
    const float* feat = (const float*)d_in[0];
    const float* wp1 = (const float*)d_in[2];
    const float* bp1 = (const float*)d_in[3];
    const float* wp2 = (const float*)d_in[4];
    const float* bp2 = (const float*)d_in[5];
    const float* wo1 = (const float*)d_in[6];
    const float* bo1 = (const float*)d_in[7];
    const float* wo2 = (const float*)d_in[8];
    const float* bo2 = (const float*)d_in[9];
    const float* wd  = (const float*)d_in[10];
    const float* bd  = (const float*)d_in[11];
    const float* wu  = (const float*)d_in[12];
    const float* bu  = (const float*)d_in[13];
    const float* wout = (const float*)d_in[14];
    const float* bout = (const float*)d_in[15];
    float* outp = (float*)d_out;

    __half *featH, *pwH, *simH, *uH, *t1H, *qH, *ctxH, *c1H, *kmH, *vH, *wH;
    float* splitF;
    cudaGetSymbolAddress((void**)&featH, g_featH);
    cudaGetSymbolAddress((void**)&pwH, g_pwH);
    cudaGetSymbolAddress((void**)&simH, g_simH);
    cudaGetSymbolAddress((void**)&uH, g_uH);
    cudaGetSymbolAddress((void**)&t1H, g_t1H);
    cudaGetSymbolAddress((void**)&qH, g_qH);
    cudaGetSymbolAddress((void**)&ctxH, g_ctxH);
    cudaGetSymbolAddress((void**)&c1H, g_c1H);
    cudaGetSymbolAddress((void**)&kmH, g_kmH);
    cudaGetSymbolAddress((void**)&vH, g_vH);
    cudaGetSymbolAddress((void**)&wH, g_wH);
    cudaGetSymbolAddress((void**)&splitF, g_split);
    __half* wp1H = wH;               // 131072
    __half* wp2H = wH + 131072;      // 65536
    __half* wo1H = wH + 196608;      // 131072
    __half* wo2H = wH + 327680;      // 65536
    __half* wdH  = wH + 393216;      // 131072
    __half* wuH  = wH + 524288;      // 131072
    __half* woutH = wH + 655360;     // 524288

    const size_t sBN = (size_t)CDIM * NDIM;
    const size_t sKN = (size_t)KEYD * NDIM;
    const size_t sCC = (size_t)CDIM * CDIM;
    const size_t sKC = (size_t)KEYD * CDIM;

    cudaFuncSetAttribute(softmax_rows16k,
                         cudaFuncAttributeMaxDynamicSharedMemorySize, 65536);
    cudaFuncSetAttribute(gemm_f16<false, false, false>,
                         cudaFuncAttributeMaxDynamicSharedMemorySize, SM_FF);
    cudaFuncSetAttribute(gemm_f16<false, false, true>,
                         cudaFuncAttributeMaxDynamicSharedMemorySize, SM_FF);
    cudaFuncSetAttribute(gemm_f16<false, true, false>,
                         cudaFuncAttributeMaxDynamicSharedMemorySize, SM_FT);
    cudaFuncSetAttribute(gemm_f16<true, false, false>,
                         cudaFuncAttributeMaxDynamicSharedMemorySize, SM_TF);

    // 0) weight conversions
    f2h<<<128, 256>>>(wp1, wp1H, 131072);
    f2h<<<64, 256>>>(wp2, wp2H, 65536);
    f2h<<<128, 256>>>(wo1, wo1H, 131072);
    f2h<<<64, 256>>>(wo2, wo2H, 65536);
    f2h<<<128, 256>>>(wd, wdH, 131072);
    f2h<<<128, 256>>>(wu, wuH, 131072);
    f2h<<<512, 256>>>(wout, woutH, 524288);

    // 1) pwH = softmax(feat rows); featH = fp16(feat)
    softmax_rows16k<<<BATCH * CDIM, 256, 65536>>>(feat, pwH, featH);

    // 2) context partials = featH * pwH^T (split-K=16) -> splitF (fp32)
    gemm_f16<false, true, false><<<dim3(4, 4, BATCH * 16), 128, SM_FT>>>(
        featH, sBN, NDIM, pwH, sBN, NDIM, nullptr, 0,
        splitF, sCC, CDIM, nullptr, 1.f, 0, 0, NDIM, 16);
    // 3) reduce -> ctxH
    {
        size_t total = (size_t)BATCH * sCC;
        reduce_split<<<(unsigned)((total + 255) / 256), 256>>>(
            splitF, ctxH, (int)sCC, 16, total);
    }
    // 4) t1 = relu(wp1 @ x + bp1) -> t1H [B,256,N]
    gemm_f16<false, false, false><<<dim3(128, 2, BATCH), 128, SM_FF>>>(
        wp1H, 0, CDIM, featH, sBN, NDIM, nullptr, 0,
        t1H, sKN, NDIM, bp1, 1.f, 1, 1, CDIM, 1);
    // 5) q = relu(wp2 @ t1 + bp2) -> qH [B,256,N]
    gemm_f16<false, false, false><<<dim3(128, 2, BATCH), 128, SM_FF>>>(
        wp2H, 0, KEYD, t1H, sKN, NDIM, nullptr, 0,
        qH, sKN, NDIM, bp2, 1.f, 1, 1, KEYD, 1);
    // 6) c1 = relu(wo1 @ context + bo1) -> c1H [B,256,512]
    gemm_f16<false, false, false><<<dim3(4, 2, BATCH), 128, SM_FF>>>(
        wo1H, 0, CDIM, ctxH, sCC, CDIM, nullptr, 0,
        c1H, sKC, CDIM, bo1, 1.f, 1, 1, CDIM, 1);
    // 7) km = relu(wo2 @ c1 + bo2) -> kmH [B,256,512]
    gemm_f16<false, false, false><<<dim3(4, 2, BATCH), 128, SM_FF>>>(
        wo2H, 0, KEYD, c1H, sKC, CDIM, nullptr, 0,
        kmH, sKC, CDIM, bo2, 1.f, 1, 1, KEYD, 1);
    // 8) v = relu(wd @ context + bd) -> vH [B,256,512]
    gemm_f16<false, false, false><<<dim3(4, 2, BATCH), 128, SM_FF>>>(
        wdH, 0, CDIM, ctxH, sCC, CDIM, nullptr, 0,
        vH, sKC, CDIM, bd, 1.f, 1, 1, CDIM, 1);
    // 9) sim = (q^T @ km) * KEY^-0.5 -> simH [B,N,512]
    gemm_f16<true, false, false><<<dim3(4, 128, BATCH), 128, SM_TF>>>(
        qH, sKN, NDIM, kmH, sKC, CDIM, nullptr, 0,
        simH, sBN, CDIM, nullptr, 0.0625f, 0, 1, KEYD, 1);
    // 10) softmax over K=512 (in place, fp16)
    softmax_k512h<<<BATCH * NDIM, 128>>>(simH);
    // 11) attn ctx = v @ sim^T -> t1H [B,256,N]
    gemm_f16<false, true, false><<<dim3(128, 2, BATCH), 128, SM_FT>>>(
        vH, sKC, CDIM, simH, sBN, CDIM, nullptr, 0,
        t1H, sKN, NDIM, nullptr, 1.f, 0, 1, CDIM, 1);
    // 12) ctx_up = relu(wu @ attn_ctx + bu) -> uH [B,512,N]
    gemm_f16<false, false, false><<<dim3(128, 4, BATCH), 128, SM_FF>>>(
        wuH, 0, KEYD, t1H, sKN, NDIM, nullptr, 0,
        uH, sBN, NDIM, bu, 1.f, 1, 1, KEYD, 1);
    // 13) out = relu(wout @ concat(ctx_up, x) + bout) -> d_out (fp32)
    gemm_f16<false, false, true><<<dim3(128, 4, BATCH), 128, SM_FF>>>(
        woutH, 0, 2 * CDIM, uH, sBN, NDIM, featH, CDIM,
        outp, sBN, NDIM, bout, 1.f, 1, 0, 2 * CDIM, 1);
}